// round 7
// baseline (speedup 1.0000x reference)
#include <cuda_runtime.h>
#include <math.h>

#define NB 8
#define NT 256
#define NDI 64
#define ND 128
#define NROWS (NB*NT)
#define NOUT 672

__device__ float g_f[NROWS*ND];
__device__ float g_k[NROWS*ND];
__device__ float g_v[NROWS*ND];
__device__ float g_theta[NROWS];
__device__ float g_eta[NROWS];
__device__ float g_alpha[NROWS];
__device__ float g_qlast[NB*ND];
__device__ float g_mlast[NB*ND];
__device__ float g_G[NB*NT*NT];     // G[b][t][tau]
__device__ float g_W[NB*NT*NT];     // W[b][t][tau] row-major (strictly lower)
__device__ float g_X[NB*8*32*32];   // inverted diag blocks
__device__ float g_Gq[NB*NT];
__device__ float g_mcoef[NB*NT];
__device__ int   g_ctr[16];

__device__ __forceinline__ float gelu_t(float x) {
    float x3 = x*x*x;
    return 0.5f*x*(1.0f + tanhf(0.79788456080286535588f*(x + 0.044715f*x3)));
}
__device__ __forceinline__ float sigmoid_f(float x) {
    return 1.0f/(1.0f + expf(-x));
}

// =====================================================================
// Launch 1: f = gelu(x @ W_b + b_b) + counter reset
// =====================================================================
__global__ __launch_bounds__(256) void fgemm_kernel(
    const float* __restrict__ A, const float* __restrict__ Bm,
    const float* __restrict__ bias)
{
    if (blockIdx.x == 0 && blockIdx.y == 0 && threadIdx.x < 16)
        g_ctr[threadIdx.x] = 0;

    __shared__ float As[16][64];
    __shared__ float Bs[16][64];
    int tid = threadIdx.x;
    int bm = blockIdx.x * 64, bn = blockIdx.y * 64;
    int ar = tid >> 2, ac = (tid & 3) * 4;
    int br = tid >> 4, bc = (tid & 15) * 4;
    int rm = (tid >> 4) * 4, rn = (tid & 15) * 4;

    float acc[4][4];
#pragma unroll
    for (int i = 0; i < 4; ++i)
#pragma unroll
        for (int j = 0; j < 4; ++j) acc[i][j] = 0.0f;

    for (int k0 = 0; k0 < NDI; k0 += 16) {
        float4 a = *(const float4*)(A + (size_t)(bm + ar) * NDI + k0 + ac);
        As[ac+0][ar]=a.x; As[ac+1][ar]=a.y; As[ac+2][ar]=a.z; As[ac+3][ar]=a.w;
        *(float4*)(&Bs[br][bc]) =
            *(const float4*)(Bm + (size_t)(k0 + br) * ND + bn + bc);
        __syncthreads();
#pragma unroll
        for (int kk = 0; kk < 16; ++kk) {
            float4 av = *(const float4*)(&As[kk][rm]);
            float4 bv = *(const float4*)(&Bs[kk][rn]);
            acc[0][0]=fmaf(av.x,bv.x,acc[0][0]); acc[0][1]=fmaf(av.x,bv.y,acc[0][1]);
            acc[0][2]=fmaf(av.x,bv.z,acc[0][2]); acc[0][3]=fmaf(av.x,bv.w,acc[0][3]);
            acc[1][0]=fmaf(av.y,bv.x,acc[1][0]); acc[1][1]=fmaf(av.y,bv.y,acc[1][1]);
            acc[1][2]=fmaf(av.y,bv.z,acc[1][2]); acc[1][3]=fmaf(av.y,bv.w,acc[1][3]);
            acc[2][0]=fmaf(av.z,bv.x,acc[2][0]); acc[2][1]=fmaf(av.z,bv.y,acc[2][1]);
            acc[2][2]=fmaf(av.z,bv.z,acc[2][2]); acc[2][3]=fmaf(av.z,bv.w,acc[2][3]);
            acc[3][0]=fmaf(av.w,bv.x,acc[3][0]); acc[3][1]=fmaf(av.w,bv.y,acc[3][1]);
            acc[3][2]=fmaf(av.w,bv.z,acc[3][2]); acc[3][3]=fmaf(av.w,bv.w,acc[3][3]);
        }
        __syncthreads();
    }
    float4 bb;
    bb.x=bias[bn+rn+0]; bb.y=bias[bn+rn+1]; bb.z=bias[bn+rn+2]; bb.w=bias[bn+rn+3];
#pragma unroll
    for (int i = 0; i < 4; ++i) {
        float4 o;
        o.x=gelu_t(acc[i][0]+bb.x); o.y=gelu_t(acc[i][1]+bb.y);
        o.z=gelu_t(acc[i][2]+bb.z); o.w=gelu_t(acc[i][3]+bb.w);
        *(float4*)(g_f + (size_t)(bm+rm+i) * ND + bn + rn) = o;
    }
}

// =====================================================================
// Launch 2: mega — k/v GEMM [0,128) + meta [128,384) + qlast [384,392)
// =====================================================================
__global__ __launch_bounds__(256) void mega_kernel(
    const float* __restrict__ Wk, const float* __restrict__ Wv,
    const float* __restrict__ Wq,
    const float* __restrict__ Wm, const float* __restrict__ bm_)
{
    __shared__ float smem_u[2 * 16 * 64];
    int idx = blockIdx.x, tid = threadIdx.x;

    if (idx < 128) {
        float (*As)[64] = (float(*)[64])smem_u;
        float (*Bs)[64] = (float(*)[64])(smem_u + 16 * 64);
        const float* Bm = (idx >> 6) ? Wv : Wk;
        float* C = (idx >> 6) ? g_v : g_k;
        int bm = (idx & 31) * 64, bn = ((idx >> 5) & 1) * 64;
        int ar = tid >> 2, ac = (tid & 3) * 4;
        int br = tid >> 4, bc = (tid & 15) * 4;
        int rm = (tid >> 4) * 4, rn = (tid & 15) * 4;

        float acc[4][4];
#pragma unroll
        for (int i = 0; i < 4; ++i)
#pragma unroll
            for (int j = 0; j < 4; ++j) acc[i][j] = 0.0f;

        for (int k0 = 0; k0 < ND; k0 += 16) {
            float4 a = *(const float4*)(g_f + (size_t)(bm + ar) * ND + k0 + ac);
            As[ac+0][ar]=a.x; As[ac+1][ar]=a.y; As[ac+2][ar]=a.z; As[ac+3][ar]=a.w;
            *(float4*)(&Bs[br][bc]) =
                *(const float4*)(Bm + (size_t)(k0 + br) * ND + bn + bc);
            __syncthreads();
#pragma unroll
            for (int kk = 0; kk < 16; ++kk) {
                float4 av = *(const float4*)(&As[kk][rm]);
                float4 bv = *(const float4*)(&Bs[kk][rn]);
                acc[0][0]=fmaf(av.x,bv.x,acc[0][0]); acc[0][1]=fmaf(av.x,bv.y,acc[0][1]);
                acc[0][2]=fmaf(av.x,bv.z,acc[0][2]); acc[0][3]=fmaf(av.x,bv.w,acc[0][3]);
                acc[1][0]=fmaf(av.y,bv.x,acc[1][0]); acc[1][1]=fmaf(av.y,bv.y,acc[1][1]);
                acc[1][2]=fmaf(av.y,bv.z,acc[1][2]); acc[1][3]=fmaf(av.y,bv.w,acc[1][3]);
                acc[2][0]=fmaf(av.z,bv.x,acc[2][0]); acc[2][1]=fmaf(av.z,bv.y,acc[2][1]);
                acc[2][2]=fmaf(av.z,bv.z,acc[2][2]); acc[2][3]=fmaf(av.z,bv.w,acc[2][3]);
                acc[3][0]=fmaf(av.w,bv.x,acc[3][0]); acc[3][1]=fmaf(av.w,bv.y,acc[3][1]);
                acc[3][2]=fmaf(av.w,bv.z,acc[3][2]); acc[3][3]=fmaf(av.w,bv.w,acc[3][3]);
            }
            __syncthreads();
        }
#pragma unroll
        for (int i = 0; i < 4; ++i) {
            float4 o; o.x=acc[i][0]; o.y=acc[i][1]; o.z=acc[i][2]; o.w=acc[i][3];
            *(float4*)(C + (size_t)(bm+rm+i) * ND + bn + rn) = o;
        }
    } else if (idx < 384) {
        int warp = tid >> 5, lane = tid & 31;
        int row = (idx - 128) * 8 + warp;
        const float4* f4 = (const float4*)g_f + (size_t)row * 32;
        float4 fv = f4[lane];
        const float* wp = Wm + lane * 12;
        float d0 = fv.x*wp[0] + fv.y*wp[3] + fv.z*wp[6] + fv.w*wp[9];
        float d1 = fv.x*wp[1] + fv.y*wp[4] + fv.z*wp[7] + fv.w*wp[10];
        float d2 = fv.x*wp[2] + fv.y*wp[5] + fv.z*wp[8] + fv.w*wp[11];
#pragma unroll
        for (int o = 16; o > 0; o >>= 1) {
            d0 += __shfl_xor_sync(0xffffffffu, d0, o);
            d1 += __shfl_xor_sync(0xffffffffu, d1, o);
            d2 += __shfl_xor_sync(0xffffffffu, d2, o);
        }
        if (lane == 0) {
            g_theta[row] = 0.01f * sigmoid_f(d0 + bm_[0]);
            g_eta[row]   =         sigmoid_f(d1 + bm_[1]);
            g_alpha[row] = 0.1f  * sigmoid_f(d2 + bm_[2]);
        }
    } else {
        int b = idx - 384;
        float* fl = smem_u;
        float* part = smem_u + 128;
        if (tid < ND) fl[tid] = g_f[(size_t)(b * NT + NT - 1) * ND + tid];
        __syncthreads();
        int j = tid & 127, h = tid >> 7;
        float acc = 0.f;
        int i0 = h * 64;
#pragma unroll 16
        for (int i = 0; i < 64; ++i)
            acc = fmaf(fl[i0 + i], Wq[(size_t)(i0 + i) * ND + j], acc);
        part[tid] = acc;
        __syncthreads();
        if (tid < ND) g_qlast[b * ND + j] = part[tid] + part[tid + 128];
    }
}

// =====================================================================
// Launch 3: per batch — G = K K^T (16 tiles) + Gq (1 block); last CTA
// writes W row-major + mcoef (plain-FMA serial tail, no shfl).
// =====================================================================
__global__ __launch_bounds__(256) void gprep_kernel()
{
    __shared__ float smem_u[2 * 16 * 64];
    __shared__ float eta_s[NT];
    __shared__ float r_s[NT];
    __shared__ float qsm[ND];
    __shared__ int sflag;

    int b = blockIdx.x / 17;
    int r = blockIdx.x % 17;
    int tid = threadIdx.x;
    const float* Kb = g_k + (size_t)b * NT * ND;
    float* Gb = g_G + (size_t)b * NT * NT;

    if (r < 16) {
        float (*As)[64] = (float(*)[64])smem_u;
        float (*Bs)[64] = (float(*)[64])(smem_u + 16 * 64);
        int I = (r >> 2) * 64, J = (r & 3) * 64;
        int ar = tid >> 2, ac = (tid & 3) * 4;
        int rm = (tid >> 4) * 4, rn = (tid & 15) * 4;

        float acc[4][4];
#pragma unroll
        for (int i = 0; i < 4; ++i)
#pragma unroll
            for (int j = 0; j < 4; ++j) acc[i][j] = 0.0f;

        for (int k0 = 0; k0 < ND; k0 += 16) {
            float4 a = *(const float4*)(Kb + (size_t)(I + ar) * ND + k0 + ac);
            As[ac+0][ar]=a.x; As[ac+1][ar]=a.y; As[ac+2][ar]=a.z; As[ac+3][ar]=a.w;
            float4 bvec = *(const float4*)(Kb + (size_t)(J + ar) * ND + k0 + ac);
            Bs[ac+0][ar]=bvec.x; Bs[ac+1][ar]=bvec.y; Bs[ac+2][ar]=bvec.z; Bs[ac+3][ar]=bvec.w;
            __syncthreads();
#pragma unroll
            for (int kk = 0; kk < 16; ++kk) {
                float4 av = *(const float4*)(&As[kk][rm]);
                float4 bv = *(const float4*)(&Bs[kk][rn]);
                acc[0][0]=fmaf(av.x,bv.x,acc[0][0]); acc[0][1]=fmaf(av.x,bv.y,acc[0][1]);
                acc[0][2]=fmaf(av.x,bv.z,acc[0][2]); acc[0][3]=fmaf(av.x,bv.w,acc[0][3]);
                acc[1][0]=fmaf(av.y,bv.x,acc[1][0]); acc[1][1]=fmaf(av.y,bv.y,acc[1][1]);
                acc[1][2]=fmaf(av.y,bv.z,acc[1][2]); acc[1][3]=fmaf(av.y,bv.w,acc[1][3]);
                acc[2][0]=fmaf(av.z,bv.x,acc[2][0]); acc[2][1]=fmaf(av.z,bv.y,acc[2][1]);
                acc[2][2]=fmaf(av.z,bv.z,acc[2][2]); acc[2][3]=fmaf(av.z,bv.w,acc[2][3]);
                acc[3][0]=fmaf(av.w,bv.x,acc[3][0]); acc[3][1]=fmaf(av.w,bv.y,acc[3][1]);
                acc[3][2]=fmaf(av.w,bv.z,acc[3][2]); acc[3][3]=fmaf(av.w,bv.w,acc[3][3]);
            }
            __syncthreads();
        }
#pragma unroll
        for (int i = 0; i < 4; ++i) {
            float4 o; o.x=acc[i][0]; o.y=acc[i][1]; o.z=acc[i][2]; o.w=acc[i][3];
            *(float4*)(Gb + (size_t)(I+rm+i) * NT + J + rn) = o;
        }
    } else {
        if (tid < ND) qsm[tid] = g_qlast[b * ND + tid];
        __syncthreads();
        const float* krow = Kb + (size_t)tid * ND;
        float acc = 0.f;
#pragma unroll 8
        for (int d = 0; d < ND; ++d) acc = fmaf(krow[d], qsm[d], acc);
        g_Gq[b * NT + tid] = acc;
    }

    __threadfence();
    __syncthreads();
    if (tid == 0) sflag = atomicAdd(&g_ctr[8 + b], 1);
    __syncthreads();
    if (sflag != 16) return;
    __threadfence();

    int tau = tid;
    eta_s[tid] = g_eta[b * NT + tid];
    r_s[tid]   = 1.0f - g_alpha[b * NT + tid];
    float th   = g_theta[b * NT + tau];
    float gq   = g_Gq[b * NT + tau];
    __syncthreads();

    float* Wb = g_W + (size_t)b * NT * NT;
    float h = 1.f, pp = 1.f;
    float gcur = Gb[NT + tau];
    // row 0 zero (it is read by inv/solve staging)
    Wb[tau] = 0.f;
    for (int t = 1; t < NT; ++t) {
        float gnext = (t < NT-1) ? Gb[(size_t)(t+1) * NT + tau] : 0.f;
        if (tau < t) {
            Wb[(size_t)t * NT + tau] = -th * gcur * h;
            pp *= eta_s[t];
            h = fmaf(r_s[t], h, pp);
        } else {
            Wb[(size_t)t * NT + tau] = 0.f;
        }
        gcur = gnext;
    }
    g_mcoef[b * NT + tau] = -th * h * gq;
}

// =====================================================================
// Launch 4: invert 32x32 unit-lower diagonal blocks via Neumann product
//   X = (I-D)^{-1} = (I+D)(I+D^2)(I+D^4)(I+D^8)(I+D^16)
// One CTA per (batch, chunk): 64 CTAs x 256 threads. All GEMMs, no shfl.
// =====================================================================
__global__ __launch_bounds__(256, 1) void inv_kernel()
{
    __shared__ __align__(16) float A0[32 * 36];
    __shared__ __align__(16) float A1[32 * 36];
    __shared__ __align__(16) float Xs[32 * 36];

    int tid = threadIdx.x;
    int b = blockIdx.x >> 3;
    int c = blockIdx.x & 7;
    const float* Wb = g_W + (size_t)b * NT * NT + (size_t)(32*c) * NT + 32*c;

    // load D (strictly lower; mask i>j), X = I + D
#pragma unroll
    for (int rep = 0; rep < 4; ++rep) {
        int idx = rep * 256 + tid;
        int i2 = idx >> 5, j2 = idx & 31;
        float w = (i2 > j2) ? Wb[(size_t)i2 * NT + j2] : 0.f;
        A0[i2 * 36 + j2] = w;
        Xs[i2 * 36 + j2] = w + ((i2 == j2) ? 1.f : 0.f);
    }
    __syncthreads();

    int r = tid >> 3;
    int c0 = (tid & 7) * 4;

    float* Acur = A0;
    float* Anxt = A1;
#pragma unroll
    for (int it = 0; it < 4; ++it) {
        // Anxt = Acur * Acur
        float4 acc = make_float4(0.f, 0.f, 0.f, 0.f);
#pragma unroll 8
        for (int kk = 0; kk < 32; ++kk) {
            float a = Acur[r * 36 + kk];
            float4 bv = *(const float4*)&Acur[kk * 36 + c0];
            acc.x = fmaf(a, bv.x, acc.x);
            acc.y = fmaf(a, bv.y, acc.y);
            acc.z = fmaf(a, bv.z, acc.z);
            acc.w = fmaf(a, bv.w, acc.w);
        }
        *(float4*)&Anxt[r * 36 + c0] = acc;
        __syncthreads();

        // X = X + X * Anxt
        float4 xa = make_float4(0.f, 0.f, 0.f, 0.f);
#pragma unroll 8
        for (int kk = 0; kk < 32; ++kk) {
            float a = Xs[r * 36 + kk];
            float4 bv = *(const float4*)&Anxt[kk * 36 + c0];
            xa.x = fmaf(a, bv.x, xa.x);
            xa.y = fmaf(a, bv.y, xa.y);
            xa.z = fmaf(a, bv.z, xa.z);
            xa.w = fmaf(a, bv.w, xa.w);
        }
        __syncthreads();
        float4 xo = *(const float4*)&Xs[r * 36 + c0];
        xo.x += xa.x; xo.y += xa.y; xo.z += xa.z; xo.w += xa.w;
        *(float4*)&Xs[r * 36 + c0] = xo;
        __syncthreads();

        float* tmp = Acur; Acur = Anxt; Anxt = tmp;
    }

    // store X coalesced
    float* Xo = g_X + (size_t)(b * 8 + c) * 1024;
#pragma unroll
    for (int rep = 0; rep < 4; ++rep) {
        int idx = rep * 256 + tid;
        Xo[idx] = Xs[(idx >> 5) * 36 + (idx & 31)];
    }
}

// =====================================================================
// Launch 5: blocked solve (left-looking GEMM + X-multiply) + fused head.
// Grid = 8 batches x 8 col-blocks (16 cols) = 64 CTAs x 256 threads.
// No shfl on any dependence chain.
// =====================================================================
__device__ __forceinline__ void head_body(
    int b, int tid,
    const float* __restrict__ W_f, const float* __restrict__ b_f,
    const float* __restrict__ W1,  const float* __restrict__ b1,
    const float* __restrict__ g1,  const float* __restrict__ be1,
    const float* __restrict__ W2,  const float* __restrict__ b2,
    float* __restrict__ out,
    float* z, float* fused, float* tbuf, float* h)
{
    if (tid < ND)        z[tid] = g_f[(size_t)(b * NT + NT - 1) * ND + tid];
    else if (tid < 2*ND) z[tid] = g_mlast[b * ND + (tid - ND)];
    __syncthreads();
    if (tid < ND) {
        float acc = b_f[tid];
#pragma unroll 8
        for (int i = 0; i < 2 * ND; ++i)
            acc = fmaf(z[i], W_f[(size_t)i * ND + tid], acc);
        float g = sigmoid_f(acc);
        fused[tid] = z[tid] * g + z[ND + tid] * (1.0f - g);
    }
    __syncthreads();
    if (tid < ND) {
        float acc = b1[tid];
#pragma unroll 8
        for (int i = 0; i < ND; ++i)
            acc = fmaf(fused[i], W1[(size_t)i * ND + tid], acc);
        tbuf[tid] = acc;
    }
    __syncthreads();
    float sum = 0.f, sq = 0.f;
#pragma unroll 8
    for (int i = 0; i < ND; ++i) { float t = tbuf[i]; sum += t; sq += t*t; }
    float mu = sum * (1.0f / ND);
    float var = sq * (1.0f / ND) - mu * mu;
    float rstd = rsqrtf(var + 1e-5f);
    if (tid < ND) {
        float ln = (tbuf[tid] - mu) * rstd * g1[tid] + be1[tid];
        h[tid] = gelu_t(ln);
    }
    __syncthreads();
    for (int o = tid; o < NOUT; o += 256) {
        float acc = b2[o];
#pragma unroll 8
        for (int i = 0; i < ND; ++i)
            acc = fmaf(h[i], W2[(size_t)i * NOUT + o], acc);
        out[b * NOUT + o] = acc;
    }
}

__global__ __launch_bounds__(256, 1) void solve_head_kernel(
    const float* __restrict__ W_f, const float* __restrict__ b_f,
    const float* __restrict__ W1,  const float* __restrict__ b1,
    const float* __restrict__ g1,  const float* __restrict__ be1,
    const float* __restrict__ W2,  const float* __restrict__ b2,
    float* __restrict__ out)
{
    __shared__ __align__(16) float Es[NT * 20];   // E[t][c], 16 cols + pad
    __shared__ float Wst[32 * 33];                // GEMM W tile / reduce buf
    __shared__ __align__(16) float Xs[32 * 36];   // inverted diag block
    __shared__ float mco[NT];
    __shared__ float z[2 * ND];
    __shared__ float fusedv[ND];
    __shared__ float tbuf[ND];
    __shared__ float hh[ND];
    __shared__ int sflag;

    int tid = threadIdx.x;
    int b  = blockIdx.x >> 3;
    int cb = blockIdx.x & 7;
    const float* Wb = g_W + (size_t)b * NT * NT;

    // ---- E = -v for this column block (float4, coalesced) ----
    {
        const float* vb = g_v + (size_t)b * NT * ND + cb * 16;
#pragma unroll
        for (int rep = 0; rep < 4; ++rep) {
            int idx = rep * 256 + tid;
            int t = idx >> 2, c4 = (idx & 3) * 4;
            float4 v4 = *(const float4*)(vb + (size_t)t * ND + c4);
            *(float4*)&Es[t * 20 + c4] = make_float4(-v4.x, -v4.y, -v4.z, -v4.w);
        }
    }
    mco[tid] = g_mcoef[b * NT + tid];
    __syncthreads();

    int gt = tid >> 3;            // 0..31
    int gh = (tid >> 2) & 1;      // k half
    int gq = tid & 3;             // col quad
    int xr = tid >> 3;            // X-mult row 0..31
    int xc = (tid & 7) * 2;       // X-mult: 2 cols per thread

    for (int C = 0; C < 8; ++C) {
        if (C > 0) {
            // ---- left GEMM: y_C = Es_C + W[32C.., 0..32C) @ Es[0..32C) ----
            float4 acc = make_float4(0.f, 0.f, 0.f, 0.f);
            for (int kt = 0; kt < C; ++kt) {
                __syncthreads();
                {
                    float4 w4 = *(const float4*)(Wb +
                        (size_t)(32*C + (tid >> 3)) * NT + kt * 32 + (tid & 7) * 4);
                    int base = (tid >> 3) * 33 + (tid & 7) * 4;
                    Wst[base+0]=w4.x; Wst[base+1]=w4.y; Wst[base+2]=w4.z; Wst[base+3]=w4.w;
                }
                __syncthreads();
#pragma unroll
                for (int kk = 0; kk < 16; ++kk) {
                    float a = Wst[gt * 33 + gh * 16 + kk];
                    float4 e4 = *(const float4*)&Es[(kt*32 + gh*16 + kk) * 20 + gq * 4];
                    acc.x = fmaf(a, e4.x, acc.x);
                    acc.y = fmaf(a, e4.y, acc.y);
                    acc.z = fmaf(a, e4.z, acc.z);
                    acc.w = fmaf(a, e4.w, acc.w);
                }
            }
            acc.x += __shfl_xor_sync(0xffffffffu, acc.x, 4);
            acc.y += __shfl_xor_sync(0xffffffffu, acc.y, 4);
            acc.z += __shfl_xor_sync(0xffffffffu, acc.z, 4);
            acc.w += __shfl_xor_sync(0xffffffffu, acc.w, 4);
            if (gh == 0) {
                float4* ep = (float4*)&Es[(32*C + gt) * 20 + gq * 4];
                float4 cur = *ep;
                cur.x += acc.x; cur.y += acc.y; cur.z += acc.z; cur.w += acc.w;
                *ep = cur;
            }
        }

        // ---- stage X_C (coalesced) ----
        __syncthreads();
        {
            const float* Xo = g_X + (size_t)(b * 8 + C) * 1024;
#pragma unroll
            for (int rep = 0; rep < 4; ++rep) {
                int idx = rep * 256 + tid;
                Xs[(idx >> 5) * 36 + (idx & 31)] = Xo[idx];
            }
        }
        __syncthreads();

        // ---- E_C = X_C @ y_C : pure smem GEMM, no serial chain ----
        {
            float a0 = 0.f, a1 = 0.f;
#pragma unroll 8
            for (int kk = 0; kk < 32; ++kk) {
                float xv = Xs[xr * 36 + kk];
                a0 = fmaf(xv, Es[(32*C + kk) * 20 + xc],     a0);
                a1 = fmaf(xv, Es[(32*C + kk) * 20 + xc + 1], a1);
            }
            __syncthreads();
            Es[(32*C + xr) * 20 + xc]     = a0;
            Es[(32*C + xr) * 20 + xc + 1] = a1;
        }
        __syncthreads();
    }

    // ---- m_last for this column block ----
    {
        int c = tid & 15, part = tid >> 4;
        float s = 0.f;
#pragma unroll
        for (int r2 = 0; r2 < 16; ++r2)
            s = fmaf(mco[part*16 + r2], Es[(part*16 + r2) * 20 + c], s);
        Wst[part * 16 + c] = s;
    }
    __syncthreads();
    if (tid < 16) {
        float s = 0.f;
#pragma unroll
        for (int p = 0; p < 16; ++p) s += Wst[p * 16 + tid];
        g_mlast[b * ND + cb * 16 + tid] = s;
    }

    // ---- fused head on last CTA of batch ----
    __threadfence();
    __syncthreads();
    if (tid == 0) sflag = atomicAdd(&g_ctr[b], 1);
    __syncthreads();
    if (sflag == 7) {
        __threadfence();
        head_body(b, tid, W_f, b_f, W1, b1, g1, be1, W2, b2, out,
                  z, fusedv, tbuf, hh);
    }
}

// ---------------- launch ----------------------------------------------------
extern "C" void kernel_launch(void* const* d_in, const int* in_sizes, int n_in,
                              void* d_out, int out_size)
{
    const float* x   = (const float*)d_in[0];
    const float* W_b = (const float*)d_in[1];
    const float* b_b = (const float*)d_in[2];
    const float* Wk  = (const float*)d_in[3];
    const float* Wv  = (const float*)d_in[4];
    const float* Wq  = (const float*)d_in[5];
    const float* W_m = (const float*)d_in[6];
    const float* b_m = (const float*)d_in[7];
    const float* W_f = (const float*)d_in[8];
    const float* b_f = (const float*)d_in[9];
    const float* W1  = (const float*)d_in[10];
    const float* b1  = (const float*)d_in[11];
    const float* g1  = (const float*)d_in[12];
    const float* be1 = (const float*)d_in[13];
    const float* W2  = (const float*)d_in[14];
    const float* b2  = (const float*)d_in[15];
    float* out = (float*)d_out;

    fgemm_kernel<<<dim3(32, 2), 256>>>(x, W_b, b_b);
    mega_kernel<<<392, 256>>>(Wk, Wv, Wq, W_m, b_m);
    gprep_kernel<<<NB * 17, 256>>>();
    inv_kernel<<<64, 256>>>();
    solve_head_kernel<<<64, 256>>>(W_f, b_f, W1, b1, g1, be1, W2, b2, out);
}

// round 8
// speedup vs baseline: 1.1239x; 1.1239x over previous
#include <cuda_runtime.h>
#include <math.h>

#define NB 8
#define NT 256
#define NDI 64
#define ND 128
#define NROWS (NB*NT)
#define NOUT 672

__device__ float g_f[NROWS*ND];
__device__ float g_k[NROWS*ND];
__device__ float g_v[NROWS*ND];
__device__ float g_theta[NROWS];
__device__ float g_eta[NROWS];
__device__ float g_alpha[NROWS];
__device__ float g_qlast[NB*ND];
__device__ float g_G[NB*NT*NT];     // G[b][t][tau]
__device__ float g_W[NB*NT*NT];     // W[b][t][tau] row-major (strictly lower)
__device__ float g_X[NB*8*32*32];   // inverted diag blocks
__device__ float g_Gq[NB*NT];
__device__ float g_mcoef[NB*NT];
__device__ int   g_ctr[16];

__device__ __forceinline__ float gelu_t(float x) {
    float x3 = x*x*x;
    return 0.5f*x*(1.0f + tanhf(0.79788456080286535588f*(x + 0.044715f*x3)));
}
__device__ __forceinline__ float sigmoid_f(float x) {
    return 1.0f/(1.0f + expf(-x));
}

// =====================================================================
// Launch 1: f = gelu(x @ W_b + b_b) + counter reset
// =====================================================================
__global__ __launch_bounds__(256) void fgemm_kernel(
    const float* __restrict__ A, const float* __restrict__ Bm,
    const float* __restrict__ bias)
{
    if (blockIdx.x == 0 && blockIdx.y == 0 && threadIdx.x < 16)
        g_ctr[threadIdx.x] = 0;

    __shared__ float As[16][64];
    __shared__ float Bs[16][64];
    int tid = threadIdx.x;
    int bm = blockIdx.x * 64, bn = blockIdx.y * 64;
    int ar = tid >> 2, ac = (tid & 3) * 4;
    int br = tid >> 4, bc = (tid & 15) * 4;
    int rm = (tid >> 4) * 4, rn = (tid & 15) * 4;

    float acc[4][4];
#pragma unroll
    for (int i = 0; i < 4; ++i)
#pragma unroll
        for (int j = 0; j < 4; ++j) acc[i][j] = 0.0f;

    for (int k0 = 0; k0 < NDI; k0 += 16) {
        float4 a = *(const float4*)(A + (size_t)(bm + ar) * NDI + k0 + ac);
        As[ac+0][ar]=a.x; As[ac+1][ar]=a.y; As[ac+2][ar]=a.z; As[ac+3][ar]=a.w;
        *(float4*)(&Bs[br][bc]) =
            *(const float4*)(Bm + (size_t)(k0 + br) * ND + bn + bc);
        __syncthreads();
#pragma unroll
        for (int kk = 0; kk < 16; ++kk) {
            float4 av = *(const float4*)(&As[kk][rm]);
            float4 bv = *(const float4*)(&Bs[kk][rn]);
            acc[0][0]=fmaf(av.x,bv.x,acc[0][0]); acc[0][1]=fmaf(av.x,bv.y,acc[0][1]);
            acc[0][2]=fmaf(av.x,bv.z,acc[0][2]); acc[0][3]=fmaf(av.x,bv.w,acc[0][3]);
            acc[1][0]=fmaf(av.y,bv.x,acc[1][0]); acc[1][1]=fmaf(av.y,bv.y,acc[1][1]);
            acc[1][2]=fmaf(av.y,bv.z,acc[1][2]); acc[1][3]=fmaf(av.y,bv.w,acc[1][3]);
            acc[2][0]=fmaf(av.z,bv.x,acc[2][0]); acc[2][1]=fmaf(av.z,bv.y,acc[2][1]);
            acc[2][2]=fmaf(av.z,bv.z,acc[2][2]); acc[2][3]=fmaf(av.z,bv.w,acc[2][3]);
            acc[3][0]=fmaf(av.w,bv.x,acc[3][0]); acc[3][1]=fmaf(av.w,bv.y,acc[3][1]);
            acc[3][2]=fmaf(av.w,bv.z,acc[3][2]); acc[3][3]=fmaf(av.w,bv.w,acc[3][3]);
        }
        __syncthreads();
    }
    float4 bb;
    bb.x=bias[bn+rn+0]; bb.y=bias[bn+rn+1]; bb.z=bias[bn+rn+2]; bb.w=bias[bn+rn+3];
#pragma unroll
    for (int i = 0; i < 4; ++i) {
        float4 o;
        o.x=gelu_t(acc[i][0]+bb.x); o.y=gelu_t(acc[i][1]+bb.y);
        o.z=gelu_t(acc[i][2]+bb.z); o.w=gelu_t(acc[i][3]+bb.w);
        *(float4*)(g_f + (size_t)(bm+rm+i) * ND + bn + rn) = o;
    }
}

// =====================================================================
// Launch 2: mega — k/v GEMM [0,128) + meta [128,384) + qlast [384,392)
// =====================================================================
__global__ __launch_bounds__(256) void mega_kernel(
    const float* __restrict__ Wk, const float* __restrict__ Wv,
    const float* __restrict__ Wq,
    const float* __restrict__ Wm, const float* __restrict__ bm_)
{
    __shared__ float smem_u[2 * 16 * 64];
    int idx = blockIdx.x, tid = threadIdx.x;

    if (idx < 128) {
        float (*As)[64] = (float(*)[64])smem_u;
        float (*Bs)[64] = (float(*)[64])(smem_u + 16 * 64);
        const float* Bm = (idx >> 6) ? Wv : Wk;
        float* C = (idx >> 6) ? g_v : g_k;
        int bm = (idx & 31) * 64, bn = ((idx >> 5) & 1) * 64;
        int ar = tid >> 2, ac = (tid & 3) * 4;
        int br = tid >> 4, bc = (tid & 15) * 4;
        int rm = (tid >> 4) * 4, rn = (tid & 15) * 4;

        float acc[4][4];
#pragma unroll
        for (int i = 0; i < 4; ++i)
#pragma unroll
            for (int j = 0; j < 4; ++j) acc[i][j] = 0.0f;

        for (int k0 = 0; k0 < ND; k0 += 16) {
            float4 a = *(const float4*)(g_f + (size_t)(bm + ar) * ND + k0 + ac);
            As[ac+0][ar]=a.x; As[ac+1][ar]=a.y; As[ac+2][ar]=a.z; As[ac+3][ar]=a.w;
            *(float4*)(&Bs[br][bc]) =
                *(const float4*)(Bm + (size_t)(k0 + br) * ND + bn + bc);
            __syncthreads();
#pragma unroll
            for (int kk = 0; kk < 16; ++kk) {
                float4 av = *(const float4*)(&As[kk][rm]);
                float4 bv = *(const float4*)(&Bs[kk][rn]);
                acc[0][0]=fmaf(av.x,bv.x,acc[0][0]); acc[0][1]=fmaf(av.x,bv.y,acc[0][1]);
                acc[0][2]=fmaf(av.x,bv.z,acc[0][2]); acc[0][3]=fmaf(av.x,bv.w,acc[0][3]);
                acc[1][0]=fmaf(av.y,bv.x,acc[1][0]); acc[1][1]=fmaf(av.y,bv.y,acc[1][1]);
                acc[1][2]=fmaf(av.y,bv.z,acc[1][2]); acc[1][3]=fmaf(av.y,bv.w,acc[1][3]);
                acc[2][0]=fmaf(av.z,bv.x,acc[2][0]); acc[2][1]=fmaf(av.z,bv.y,acc[2][1]);
                acc[2][2]=fmaf(av.z,bv.z,acc[2][2]); acc[2][3]=fmaf(av.z,bv.w,acc[2][3]);
                acc[3][0]=fmaf(av.w,bv.x,acc[3][0]); acc[3][1]=fmaf(av.w,bv.y,acc[3][1]);
                acc[3][2]=fmaf(av.w,bv.z,acc[3][2]); acc[3][3]=fmaf(av.w,bv.w,acc[3][3]);
            }
            __syncthreads();
        }
#pragma unroll
        for (int i = 0; i < 4; ++i) {
            float4 o; o.x=acc[i][0]; o.y=acc[i][1]; o.z=acc[i][2]; o.w=acc[i][3];
            *(float4*)(C + (size_t)(bm+rm+i) * ND + bn + rn) = o;
        }
    } else if (idx < 384) {
        int warp = tid >> 5, lane = tid & 31;
        int row = (idx - 128) * 8 + warp;
        const float4* f4 = (const float4*)g_f + (size_t)row * 32;
        float4 fv = f4[lane];
        const float* wp = Wm + lane * 12;
        float d0 = fv.x*wp[0] + fv.y*wp[3] + fv.z*wp[6] + fv.w*wp[9];
        float d1 = fv.x*wp[1] + fv.y*wp[4] + fv.z*wp[7] + fv.w*wp[10];
        float d2 = fv.x*wp[2] + fv.y*wp[5] + fv.z*wp[8] + fv.w*wp[11];
#pragma unroll
        for (int o = 16; o > 0; o >>= 1) {
            d0 += __shfl_xor_sync(0xffffffffu, d0, o);
            d1 += __shfl_xor_sync(0xffffffffu, d1, o);
            d2 += __shfl_xor_sync(0xffffffffu, d2, o);
        }
        if (lane == 0) {
            g_theta[row] = 0.01f * sigmoid_f(d0 + bm_[0]);
            g_eta[row]   =         sigmoid_f(d1 + bm_[1]);
            g_alpha[row] = 0.1f  * sigmoid_f(d2 + bm_[2]);
        }
    } else {
        int b = idx - 384;
        float* fl = smem_u;
        float* part = smem_u + 128;
        if (tid < ND) fl[tid] = g_f[(size_t)(b * NT + NT - 1) * ND + tid];
        __syncthreads();
        int j = tid & 127, h = tid >> 7;
        float acc = 0.f;
        int i0 = h * 64;
#pragma unroll 16
        for (int i = 0; i < 64; ++i)
            acc = fmaf(fl[i0 + i], Wq[(size_t)(i0 + i) * ND + j], acc);
        part[tid] = acc;
        __syncthreads();
        if (tid < ND) g_qlast[b * ND + j] = part[tid] + part[tid + 128];
    }
}

// =====================================================================
// Launch 3: per batch — G = K K^T (16 tiles) + Gq (1 block); last CTA
// writes W row-major + mcoef (plain-FMA serial tail, no shfl).
// =====================================================================
__global__ __launch_bounds__(256) void gprep_kernel()
{
    __shared__ float smem_u[2 * 16 * 64];
    __shared__ float eta_s[NT];
    __shared__ float r_s[NT];
    __shared__ float qsm[ND];
    __shared__ int sflag;

    int b = blockIdx.x / 17;
    int r = blockIdx.x % 17;
    int tid = threadIdx.x;
    const float* Kb = g_k + (size_t)b * NT * ND;
    float* Gb = g_G + (size_t)b * NT * NT;

    if (r < 16) {
        float (*As)[64] = (float(*)[64])smem_u;
        float (*Bs)[64] = (float(*)[64])(smem_u + 16 * 64);
        int I = (r >> 2) * 64, J = (r & 3) * 64;
        int ar = tid >> 2, ac = (tid & 3) * 4;
        int rm = (tid >> 4) * 4, rn = (tid & 15) * 4;

        float acc[4][4];
#pragma unroll
        for (int i = 0; i < 4; ++i)
#pragma unroll
            for (int j = 0; j < 4; ++j) acc[i][j] = 0.0f;

        for (int k0 = 0; k0 < ND; k0 += 16) {
            float4 a = *(const float4*)(Kb + (size_t)(I + ar) * ND + k0 + ac);
            As[ac+0][ar]=a.x; As[ac+1][ar]=a.y; As[ac+2][ar]=a.z; As[ac+3][ar]=a.w;
            float4 bvec = *(const float4*)(Kb + (size_t)(J + ar) * ND + k0 + ac);
            Bs[ac+0][ar]=bvec.x; Bs[ac+1][ar]=bvec.y; Bs[ac+2][ar]=bvec.z; Bs[ac+3][ar]=bvec.w;
            __syncthreads();
#pragma unroll
            for (int kk = 0; kk < 16; ++kk) {
                float4 av = *(const float4*)(&As[kk][rm]);
                float4 bv = *(const float4*)(&Bs[kk][rn]);
                acc[0][0]=fmaf(av.x,bv.x,acc[0][0]); acc[0][1]=fmaf(av.x,bv.y,acc[0][1]);
                acc[0][2]=fmaf(av.x,bv.z,acc[0][2]); acc[0][3]=fmaf(av.x,bv.w,acc[0][3]);
                acc[1][0]=fmaf(av.y,bv.x,acc[1][0]); acc[1][1]=fmaf(av.y,bv.y,acc[1][1]);
                acc[1][2]=fmaf(av.y,bv.z,acc[1][2]); acc[1][3]=fmaf(av.y,bv.w,acc[1][3]);
                acc[2][0]=fmaf(av.z,bv.x,acc[2][0]); acc[2][1]=fmaf(av.z,bv.y,acc[2][1]);
                acc[2][2]=fmaf(av.z,bv.z,acc[2][2]); acc[2][3]=fmaf(av.z,bv.w,acc[2][3]);
                acc[3][0]=fmaf(av.w,bv.x,acc[3][0]); acc[3][1]=fmaf(av.w,bv.y,acc[3][1]);
                acc[3][2]=fmaf(av.w,bv.z,acc[3][2]); acc[3][3]=fmaf(av.w,bv.w,acc[3][3]);
            }
            __syncthreads();
        }
#pragma unroll
        for (int i = 0; i < 4; ++i) {
            float4 o; o.x=acc[i][0]; o.y=acc[i][1]; o.z=acc[i][2]; o.w=acc[i][3];
            *(float4*)(Gb + (size_t)(I+rm+i) * NT + J + rn) = o;
        }
    } else {
        if (tid < ND) qsm[tid] = g_qlast[b * ND + tid];
        __syncthreads();
        const float* krow = Kb + (size_t)tid * ND;
        float acc = 0.f;
#pragma unroll 8
        for (int d = 0; d < ND; ++d) acc = fmaf(krow[d], qsm[d], acc);
        g_Gq[b * NT + tid] = acc;
    }

    __threadfence();
    __syncthreads();
    if (tid == 0) sflag = atomicAdd(&g_ctr[8 + b], 1);
    __syncthreads();
    if (sflag != 16) return;
    __threadfence();

    int tau = tid;
    eta_s[tid] = g_eta[b * NT + tid];
    r_s[tid]   = 1.0f - g_alpha[b * NT + tid];
    float th   = g_theta[b * NT + tau];
    float gq   = g_Gq[b * NT + tau];
    __syncthreads();

    float* Wb = g_W + (size_t)b * NT * NT;
    float h = 1.f, pp = 1.f;
    float gcur = Gb[NT + tau];
    Wb[tau] = 0.f;
    for (int t = 1; t < NT; ++t) {
        float gnext = (t < NT-1) ? Gb[(size_t)(t+1) * NT + tau] : 0.f;
        if (tau < t) {
            Wb[(size_t)t * NT + tau] = -th * gcur * h;
            pp *= eta_s[t];
            h = fmaf(r_s[t], h, pp);
        } else {
            Wb[(size_t)t * NT + tau] = 0.f;
        }
        gcur = gnext;
    }
    g_mcoef[b * NT + tau] = -th * h * gq;
}

// =====================================================================
// Launch 4: invert 32x32 unit-lower diagonal blocks (Neumann product)
// =====================================================================
__global__ __launch_bounds__(256, 1) void inv_kernel()
{
    __shared__ __align__(16) float A0[32 * 36];
    __shared__ __align__(16) float A1[32 * 36];
    __shared__ __align__(16) float Xs[32 * 36];

    int tid = threadIdx.x;
    int b = blockIdx.x >> 3;
    int c = blockIdx.x & 7;
    const float* Wb = g_W + (size_t)b * NT * NT + (size_t)(32*c) * NT + 32*c;

#pragma unroll
    for (int rep = 0; rep < 4; ++rep) {
        int idx = rep * 256 + tid;
        int i2 = idx >> 5, j2 = idx & 31;
        float w = (i2 > j2) ? Wb[(size_t)i2 * NT + j2] : 0.f;
        A0[i2 * 36 + j2] = w;
        Xs[i2 * 36 + j2] = w + ((i2 == j2) ? 1.f : 0.f);
    }
    __syncthreads();

    int r = tid >> 3;
    int c0 = (tid & 7) * 4;

    float* Acur = A0;
    float* Anxt = A1;
#pragma unroll
    for (int it = 0; it < 4; ++it) {
        float4 acc = make_float4(0.f, 0.f, 0.f, 0.f);
#pragma unroll 8
        for (int kk = 0; kk < 32; ++kk) {
            float a = Acur[r * 36 + kk];
            float4 bv = *(const float4*)&Acur[kk * 36 + c0];
            acc.x = fmaf(a, bv.x, acc.x);
            acc.y = fmaf(a, bv.y, acc.y);
            acc.z = fmaf(a, bv.z, acc.z);
            acc.w = fmaf(a, bv.w, acc.w);
        }
        *(float4*)&Anxt[r * 36 + c0] = acc;
        __syncthreads();

        float4 xa = make_float4(0.f, 0.f, 0.f, 0.f);
#pragma unroll 8
        for (int kk = 0; kk < 32; ++kk) {
            float a = Xs[r * 36 + kk];
            float4 bv = *(const float4*)&Anxt[kk * 36 + c0];
            xa.x = fmaf(a, bv.x, xa.x);
            xa.y = fmaf(a, bv.y, xa.y);
            xa.z = fmaf(a, bv.z, xa.z);
            xa.w = fmaf(a, bv.w, xa.w);
        }
        __syncthreads();
        float4 xo = *(const float4*)&Xs[r * 36 + c0];
        xo.x += xa.x; xo.y += xa.y; xo.z += xa.z; xo.w += xa.w;
        *(float4*)&Xs[r * 36 + c0] = xo;
        __syncthreads();

        float* tmp = Acur; Acur = Anxt; Anxt = tmp;
    }

    float* Xo = g_X + (size_t)(b * 8 + c) * 1024;
#pragma unroll
    for (int rep = 0; rep < 4; ++rep) {
        int idx = rep * 256 + tid;
        Xo[idx] = Xs[(idx >> 5) * 36 + (idx & 31)];
    }
}

// =====================================================================
// Launch 5: z-solve + head. One CTA per batch (8 CTAs x 256 threads).
//   (I - W^T) z = mcoef   (back-substitution over 8 chunks, X^T apply)
//   m_last = -V^T z ; then the full head for this batch.
// =====================================================================
__global__ __launch_bounds__(256, 1) void zsolve_head_kernel(
    const float* __restrict__ W_f, const float* __restrict__ b_f,
    const float* __restrict__ W1,  const float* __restrict__ b1,
    const float* __restrict__ g1,  const float* __restrict__ be1,
    const float* __restrict__ W2,  const float* __restrict__ b2,
    float* __restrict__ out)
{
    __shared__ float Xall[8][32 * 33];   // all inverted diag blocks
    __shared__ float zs[NT];
    __shared__ float mc[NT];
    __shared__ float rbuf[32];
    __shared__ float pbuf[8][33];
    __shared__ float zh[2 * ND];         // f_last | m_last (and partials)
    __shared__ float red[2 * ND];
    __shared__ float fusedv[ND];
    __shared__ float tbuf[ND];
    __shared__ float hh[ND];

    int tid = threadIdx.x;
    int b = blockIdx.x;
    const float* Wb = g_W + (size_t)b * NT * NT;

    // stage all X blocks (coalesced)
    {
        const float* Xo = g_X + (size_t)b * 8 * 1024;
#pragma unroll
        for (int rep = 0; rep < 32; ++rep) {
            int idx = rep * 256 + tid;          // 8192 total
            int cc = idx >> 10, r2 = (idx >> 5) & 31, j2 = idx & 31;
            Xall[cc][r2 * 33 + j2] = Xo[idx];
        }
    }
    mc[tid] = g_mcoef[b * NT + tid];
    __syncthreads();

    int u = tid & 31, w = tid >> 5;

    // ---- back-substitution, chunk C = 7 .. 0 ----
    for (int C = 7; C >= 0; --C) {
        // partial dots: rhs[u] += sum_{t >= 32(C+1)} W[t][32C+u] * z[t]
        float acc = 0.f;
        int t0 = 32 * (C + 1);
        int nj = 4 * (7 - C);
#pragma unroll 4
        for (int j = 0; j < nj; ++j) {
            int t = t0 + j * 8 + w;
            acc = fmaf(Wb[(size_t)t * NT + 32*C + u], zs[t], acc);
        }
        pbuf[w][u] = acc;
        __syncthreads();
        if (tid < 32) {
            float s = mc[32*C + tid];
#pragma unroll
            for (int p = 0; p < 8; ++p) s += pbuf[p][tid];
            rbuf[tid] = s;
        }
        __syncthreads();
        // z_C = X_C^T rhs : z[32C+u] = sum_kk X[kk][u] * rhs[kk]
        {
            float a = 0.f;
#pragma unroll
            for (int q = 0; q < 4; ++q) {
                int kk = w * 4 + q;
                a = fmaf(Xall[C][kk * 33 + u], rbuf[kk], a);
            }
            pbuf[w][u] = a;
        }
        __syncthreads();
        if (tid < 32) {
            float s = 0.f;
#pragma unroll
            for (int p = 0; p < 8; ++p) s += pbuf[p][tid];
            zs[32*C + tid] = s;
        }
        __syncthreads();
    }

    // ---- m_last = -V^T z (2-way K split) ----
    {
        int i = tid & 127, hf = tid >> 7;
        const float* vb = g_v + (size_t)b * NT * ND;
        float a = 0.f;
        int tb = hf * 128;
#pragma unroll 8
        for (int t = 0; t < 128; ++t)
            a = fmaf(vb[(size_t)(tb + t) * ND + i], zs[tb + t], a);
        red[hf * ND + i] = a;
    }
    __syncthreads();

    // ---- head ----
    if (tid < ND) {
        zh[ND + tid] = -(red[tid] + red[ND + tid]);                 // m_last
        zh[tid] = g_f[(size_t)(b * NT + NT - 1) * ND + tid];        // f_last
    }
    __syncthreads();

    // gate = sigmoid([f|m] @ W_f + b_f), 2-way K split
    {
        int o = tid & 127, hf = tid >> 7;
        float acc = 0.f;
        int ib = hf * 128;
#pragma unroll 8
        for (int i = 0; i < 128; ++i)
            acc = fmaf(zh[ib + i], W_f[(size_t)(ib + i) * ND + o], acc);
        red[hf * ND + o] = acc;
    }
    __syncthreads();
    if (tid < ND) {
        float g = sigmoid_f(red[tid] + red[ND + tid] + b_f[tid]);
        fusedv[tid] = zh[tid] * g + zh[ND + tid] * (1.0f - g);
    }
    __syncthreads();

    // t = fused @ W1 + b1, 2-way K split
    {
        int o = tid & 127, hf = tid >> 7;
        float acc = 0.f;
        int ib = hf * 64;
#pragma unroll 8
        for (int i = 0; i < 64; ++i)
            acc = fmaf(fusedv[ib + i], W1[(size_t)(ib + i) * ND + o], acc);
        red[hf * ND + o] = acc;
    }
    __syncthreads();
    if (tid < ND) tbuf[tid] = red[tid] + red[ND + tid] + b1[tid];
    __syncthreads();

    // layernorm + gelu
    float sum = 0.f, sq = 0.f;
#pragma unroll 8
    for (int i = 0; i < ND; ++i) { float t = tbuf[i]; sum += t; sq += t*t; }
    float mu = sum * (1.0f / ND);
    float var = sq * (1.0f / ND) - mu * mu;
    float rstd = rsqrtf(var + 1e-5f);
    if (tid < ND) {
        float ln = (tbuf[tid] - mu) * rstd * g1[tid] + be1[tid];
        hh[tid] = gelu_t(ln);
    }
    __syncthreads();

    // out = h @ W2 + b2
    for (int o = tid; o < NOUT; o += 256) {
        float acc = b2[o];
#pragma unroll 8
        for (int i = 0; i < ND; ++i)
            acc = fmaf(hh[i], W2[(size_t)i * NOUT + o], acc);
        out[b * NOUT + o] = acc;
    }
}

// ---------------- launch ----------------------------------------------------
extern "C" void kernel_launch(void* const* d_in, const int* in_sizes, int n_in,
                              void* d_out, int out_size)
{
    const float* x   = (const float*)d_in[0];
    const float* W_b = (const float*)d_in[1];
    const float* b_b = (const float*)d_in[2];
    const float* Wk  = (const float*)d_in[3];
    const float* Wv  = (const float*)d_in[4];
    const float* Wq  = (const float*)d_in[5];
    const float* W_m = (const float*)d_in[6];
    const float* b_m = (const float*)d_in[7];
    const float* W_f = (const float*)d_in[8];
    const float* b_f = (const float*)d_in[9];
    const float* W1  = (const float*)d_in[10];
    const float* b1  = (const float*)d_in[11];
    const float* g1  = (const float*)d_in[12];
    const float* be1 = (const float*)d_in[13];
    const float* W2  = (const float*)d_in[14];
    const float* b2  = (const float*)d_in[15];
    float* out = (float*)d_out;

    fgemm_kernel<<<dim3(32, 2), 256>>>(x, W_b, b_b);
    mega_kernel<<<392, 256>>>(Wk, Wv, Wq, W_m, b_m);
    gprep_kernel<<<NB * 17, 256>>>();
    inv_kernel<<<64, 256>>>();
    zsolve_head_kernel<<<NB, 256>>>(W_f, b_f, W1, b1, g1, be1, W2, b2, out);
}

// round 9
// speedup vs baseline: 1.4389x; 1.2803x over previous
#include <cuda_runtime.h>
#include <math.h>

#define NB 8
#define NT 256
#define NDI 64
#define ND 128
#define NROWS (NB*NT)
#define NOUT 672

__device__ float g_f[NROWS*ND];
__device__ float g_k[NROWS*ND];
__device__ float g_v[NROWS*ND];
__device__ float g_theta[NROWS];
__device__ float g_eta[NROWS];
__device__ float g_alpha[NROWS];
__device__ float g_qlast[NB*ND];
__device__ float g_G[NB*NT*NT];     // G[b][t][tau]
__device__ float g_X[NB*8*32*32];   // inverted diag blocks
__device__ float g_Gq[NB*NT];
__device__ float g_mcoef[NB*NT];
__device__ float g_A[NB*NT];        // per-row chunk factor A_j
__device__ float g_B[NB*NT];        // per-row chunk factor B_j
__device__ float g_Hc[NB*8*NT];     // boundary H state  [b][C][tau]
__device__ float g_PPc[NB*8*NT];    // boundary PP state [b][C][tau]
__device__ int   g_ctr[16];

__device__ __forceinline__ float gelu_t(float x) {
    float x3 = x*x*x;
    return 0.5f*x*(1.0f + tanhf(0.79788456080286535588f*(x + 0.044715f*x3)));
}
__device__ __forceinline__ float sigmoid_f(float x) {
    return 1.0f/(1.0f + expf(-x));
}

// =====================================================================
// Launch 1: f = gelu(x @ W_b + b_b) + counter reset
// =====================================================================
__global__ __launch_bounds__(256) void fgemm_kernel(
    const float* __restrict__ A, const float* __restrict__ Bm,
    const float* __restrict__ bias)
{
    if (blockIdx.x == 0 && blockIdx.y == 0 && threadIdx.x < 16)
        g_ctr[threadIdx.x] = 0;

    __shared__ float As[16][64];
    __shared__ float Bs[16][64];
    int tid = threadIdx.x;
    int bm = blockIdx.x * 64, bn = blockIdx.y * 64;
    int ar = tid >> 2, ac = (tid & 3) * 4;
    int br = tid >> 4, bc = (tid & 15) * 4;
    int rm = (tid >> 4) * 4, rn = (tid & 15) * 4;

    float acc[4][4];
#pragma unroll
    for (int i = 0; i < 4; ++i)
#pragma unroll
        for (int j = 0; j < 4; ++j) acc[i][j] = 0.0f;

    for (int k0 = 0; k0 < NDI; k0 += 16) {
        float4 a = *(const float4*)(A + (size_t)(bm + ar) * NDI + k0 + ac);
        As[ac+0][ar]=a.x; As[ac+1][ar]=a.y; As[ac+2][ar]=a.z; As[ac+3][ar]=a.w;
        *(float4*)(&Bs[br][bc]) =
            *(const float4*)(Bm + (size_t)(k0 + br) * ND + bn + bc);
        __syncthreads();
#pragma unroll
        for (int kk = 0; kk < 16; ++kk) {
            float4 av = *(const float4*)(&As[kk][rm]);
            float4 bv = *(const float4*)(&Bs[kk][rn]);
            acc[0][0]=fmaf(av.x,bv.x,acc[0][0]); acc[0][1]=fmaf(av.x,bv.y,acc[0][1]);
            acc[0][2]=fmaf(av.x,bv.z,acc[0][2]); acc[0][3]=fmaf(av.x,bv.w,acc[0][3]);
            acc[1][0]=fmaf(av.y,bv.x,acc[1][0]); acc[1][1]=fmaf(av.y,bv.y,acc[1][1]);
            acc[1][2]=fmaf(av.y,bv.z,acc[1][2]); acc[1][3]=fmaf(av.y,bv.w,acc[1][3]);
            acc[2][0]=fmaf(av.z,bv.x,acc[2][0]); acc[2][1]=fmaf(av.z,bv.y,acc[2][1]);
            acc[2][2]=fmaf(av.z,bv.z,acc[2][2]); acc[2][3]=fmaf(av.z,bv.w,acc[2][3]);
            acc[3][0]=fmaf(av.w,bv.x,acc[3][0]); acc[3][1]=fmaf(av.w,bv.y,acc[3][1]);
            acc[3][2]=fmaf(av.w,bv.z,acc[3][2]); acc[3][3]=fmaf(av.w,bv.w,acc[3][3]);
        }
        __syncthreads();
    }
    float4 bb;
    bb.x=bias[bn+rn+0]; bb.y=bias[bn+rn+1]; bb.z=bias[bn+rn+2]; bb.w=bias[bn+rn+3];
#pragma unroll
    for (int i = 0; i < 4; ++i) {
        float4 o;
        o.x=gelu_t(acc[i][0]+bb.x); o.y=gelu_t(acc[i][1]+bb.y);
        o.z=gelu_t(acc[i][2]+bb.z); o.w=gelu_t(acc[i][3]+bb.w);
        *(float4*)(g_f + (size_t)(bm+rm+i) * ND + bn + rn) = o;
    }
}

// =====================================================================
// Launch 2: mega — k/v GEMM [0,128) + meta [128,384) + qlast [384,392)
// =====================================================================
__global__ __launch_bounds__(256) void mega_kernel(
    const float* __restrict__ Wk, const float* __restrict__ Wv,
    const float* __restrict__ Wq,
    const float* __restrict__ Wm, const float* __restrict__ bm_)
{
    __shared__ float smem_u[2 * 16 * 64];
    int idx = blockIdx.x, tid = threadIdx.x;

    if (idx < 128) {
        float (*As)[64] = (float(*)[64])smem_u;
        float (*Bs)[64] = (float(*)[64])(smem_u + 16 * 64);
        const float* Bm = (idx >> 6) ? Wv : Wk;
        float* C = (idx >> 6) ? g_v : g_k;
        int bm = (idx & 31) * 64, bn = ((idx >> 5) & 1) * 64;
        int ar = tid >> 2, ac = (tid & 3) * 4;
        int br = tid >> 4, bc = (tid & 15) * 4;
        int rm = (tid >> 4) * 4, rn = (tid & 15) * 4;

        float acc[4][4];
#pragma unroll
        for (int i = 0; i < 4; ++i)
#pragma unroll
            for (int j = 0; j < 4; ++j) acc[i][j] = 0.0f;

        for (int k0 = 0; k0 < ND; k0 += 16) {
            float4 a = *(const float4*)(g_f + (size_t)(bm + ar) * ND + k0 + ac);
            As[ac+0][ar]=a.x; As[ac+1][ar]=a.y; As[ac+2][ar]=a.z; As[ac+3][ar]=a.w;
            *(float4*)(&Bs[br][bc]) =
                *(const float4*)(Bm + (size_t)(k0 + br) * ND + bn + bc);
            __syncthreads();
#pragma unroll
            for (int kk = 0; kk < 16; ++kk) {
                float4 av = *(const float4*)(&As[kk][rm]);
                float4 bv = *(const float4*)(&Bs[kk][rn]);
                acc[0][0]=fmaf(av.x,bv.x,acc[0][0]); acc[0][1]=fmaf(av.x,bv.y,acc[0][1]);
                acc[0][2]=fmaf(av.x,bv.z,acc[0][2]); acc[0][3]=fmaf(av.x,bv.w,acc[0][3]);
                acc[1][0]=fmaf(av.y,bv.x,acc[1][0]); acc[1][1]=fmaf(av.y,bv.y,acc[1][1]);
                acc[1][2]=fmaf(av.y,bv.z,acc[1][2]); acc[1][3]=fmaf(av.y,bv.w,acc[1][3]);
                acc[2][0]=fmaf(av.z,bv.x,acc[2][0]); acc[2][1]=fmaf(av.z,bv.y,acc[2][1]);
                acc[2][2]=fmaf(av.z,bv.z,acc[2][2]); acc[2][3]=fmaf(av.z,bv.w,acc[2][3]);
                acc[3][0]=fmaf(av.w,bv.x,acc[3][0]); acc[3][1]=fmaf(av.w,bv.y,acc[3][1]);
                acc[3][2]=fmaf(av.w,bv.z,acc[3][2]); acc[3][3]=fmaf(av.w,bv.w,acc[3][3]);
            }
            __syncthreads();
        }
#pragma unroll
        for (int i = 0; i < 4; ++i) {
            float4 o; o.x=acc[i][0]; o.y=acc[i][1]; o.z=acc[i][2]; o.w=acc[i][3];
            *(float4*)(C + (size_t)(bm+rm+i) * ND + bn + rn) = o;
        }
    } else if (idx < 384) {
        int warp = tid >> 5, lane = tid & 31;
        int row = (idx - 128) * 8 + warp;
        const float4* f4 = (const float4*)g_f + (size_t)row * 32;
        float4 fv = f4[lane];
        const float* wp = Wm + lane * 12;
        float d0 = fv.x*wp[0] + fv.y*wp[3] + fv.z*wp[6] + fv.w*wp[9];
        float d1 = fv.x*wp[1] + fv.y*wp[4] + fv.z*wp[7] + fv.w*wp[10];
        float d2 = fv.x*wp[2] + fv.y*wp[5] + fv.z*wp[8] + fv.w*wp[11];
#pragma unroll
        for (int o = 16; o > 0; o >>= 1) {
            d0 += __shfl_xor_sync(0xffffffffu, d0, o);
            d1 += __shfl_xor_sync(0xffffffffu, d1, o);
            d2 += __shfl_xor_sync(0xffffffffu, d2, o);
        }
        if (lane == 0) {
            g_theta[row] = 0.01f * sigmoid_f(d0 + bm_[0]);
            g_eta[row]   =         sigmoid_f(d1 + bm_[1]);
            g_alpha[row] = 0.1f  * sigmoid_f(d2 + bm_[2]);
        }
    } else {
        int b = idx - 384;
        float* fl = smem_u;
        float* part = smem_u + 128;
        if (tid < ND) fl[tid] = g_f[(size_t)(b * NT + NT - 1) * ND + tid];
        __syncthreads();
        int j = tid & 127, h = tid >> 7;
        float acc = 0.f;
        int i0 = h * 64;
#pragma unroll 16
        for (int i = 0; i < 64; ++i)
            acc = fmaf(fl[i0 + i], Wq[(size_t)(i0 + i) * ND + j], acc);
        part[tid] = acc;
        __syncthreads();
        if (tid < ND) g_qlast[b * ND + j] = part[tid] + part[tid + 128];
    }
}

// =====================================================================
// Launch 3: per batch — G = K K^T (16 tiles) + Gq (1 block); last CTA
// computes chunk-factored recurrence constants (no W materialization).
// =====================================================================
__global__ __launch_bounds__(256) void gprep_kernel()
{
    __shared__ float smem_u[2 * 16 * 64];
    __shared__ float eta_s[NT];
    __shared__ float r_s[NT];
    __shared__ float aRow[NT];
    __shared__ float bRow[NT];
    __shared__ float A32s[8], B32s[8], E32s[8];
    __shared__ float qsm[ND];
    __shared__ int sflag;

    int b = blockIdx.x / 17;
    int r = blockIdx.x % 17;
    int tid = threadIdx.x;
    const float* Kb = g_k + (size_t)b * NT * ND;
    float* Gb = g_G + (size_t)b * NT * NT;

    if (r < 16) {
        float (*As)[64] = (float(*)[64])smem_u;
        float (*Bs)[64] = (float(*)[64])(smem_u + 16 * 64);
        int I = (r >> 2) * 64, J = (r & 3) * 64;
        int ar = tid >> 2, ac = (tid & 3) * 4;
        int rm = (tid >> 4) * 4, rn = (tid & 15) * 4;

        float acc[4][4];
#pragma unroll
        for (int i = 0; i < 4; ++i)
#pragma unroll
            for (int j = 0; j < 4; ++j) acc[i][j] = 0.0f;

        for (int k0 = 0; k0 < ND; k0 += 16) {
            float4 a = *(const float4*)(Kb + (size_t)(I + ar) * ND + k0 + ac);
            As[ac+0][ar]=a.x; As[ac+1][ar]=a.y; As[ac+2][ar]=a.z; As[ac+3][ar]=a.w;
            float4 bvec = *(const float4*)(Kb + (size_t)(J + ar) * ND + k0 + ac);
            Bs[ac+0][ar]=bvec.x; Bs[ac+1][ar]=bvec.y; Bs[ac+2][ar]=bvec.z; Bs[ac+3][ar]=bvec.w;
            __syncthreads();
#pragma unroll
            for (int kk = 0; kk < 16; ++kk) {
                float4 av = *(const float4*)(&As[kk][rm]);
                float4 bv = *(const float4*)(&Bs[kk][rn]);
                acc[0][0]=fmaf(av.x,bv.x,acc[0][0]); acc[0][1]=fmaf(av.x,bv.y,acc[0][1]);
                acc[0][2]=fmaf(av.x,bv.z,acc[0][2]); acc[0][3]=fmaf(av.x,bv.w,acc[0][3]);
                acc[1][0]=fmaf(av.y,bv.x,acc[1][0]); acc[1][1]=fmaf(av.y,bv.y,acc[1][1]);
                acc[1][2]=fmaf(av.y,bv.z,acc[1][2]); acc[1][3]=fmaf(av.y,bv.w,acc[1][3]);
                acc[2][0]=fmaf(av.z,bv.x,acc[2][0]); acc[2][1]=fmaf(av.z,bv.y,acc[2][1]);
                acc[2][2]=fmaf(av.z,bv.z,acc[2][2]); acc[2][3]=fmaf(av.z,bv.w,acc[2][3]);
                acc[3][0]=fmaf(av.w,bv.x,acc[3][0]); acc[3][1]=fmaf(av.w,bv.y,acc[3][1]);
                acc[3][2]=fmaf(av.w,bv.z,acc[3][2]); acc[3][3]=fmaf(av.w,bv.w,acc[3][3]);
            }
            __syncthreads();
        }
#pragma unroll
        for (int i = 0; i < 4; ++i) {
            float4 o; o.x=acc[i][0]; o.y=acc[i][1]; o.z=acc[i][2]; o.w=acc[i][3];
            *(float4*)(Gb + (size_t)(I+rm+i) * NT + J + rn) = o;
        }
    } else {
        if (tid < ND) qsm[tid] = g_qlast[b * ND + tid];
        __syncthreads();
        const float* krow = Kb + (size_t)tid * ND;
        float acc = 0.f;
#pragma unroll 8
        for (int d = 0; d < ND; ++d) acc = fmaf(krow[d], qsm[d], acc);
        g_Gq[b * NT + tid] = acc;
    }

    __threadfence();
    __syncthreads();
    if (tid == 0) sflag = atomicAdd(&g_ctr[8 + b], 1);
    __syncthreads();
    if (sflag != 16) return;
    __threadfence();

    // ---- chunk-factored recurrence constants (cheap, smem-only) ----
    int tau = tid;
    eta_s[tid] = g_eta[b * NT + tid];
    r_s[tid]   = 1.0f - g_alpha[b * NT + tid];
    float th   = g_theta[b * NT + tau];
    float gq   = g_Gq[b * NT + tau];
    __syncthreads();

    // per-chunk row constants (threads 0..7, 32 serial steps each)
    if (tid < 8) {
        int c0 = tid * 32;
        float A = 1.f, Bv = 0.f, E = 1.f;
        for (int j = 0; j < 32; ++j) {
            aRow[c0 + j] = A;
            bRow[c0 + j] = Bv;
            E *= eta_s[c0 + j];
            Bv = fmaf(r_s[c0 + j], Bv, E);
            A *= r_s[c0 + j];
        }
        A32s[tid] = A; B32s[tid] = Bv; E32s[tid] = E;
    }
    __syncthreads();

    // per-tau boundary states
    int Ct = tau >> 5;
    float h = 1.f, pp = 1.f;
    int c1 = 32 * (Ct + 1);
    for (int t = tau + 1; t < c1; ++t) {      // <=31 local steps
        pp *= eta_s[t];
        h = fmaf(r_s[t], h, pp);
    }
    for (int C = Ct + 1; C < 8; ++C) {        // <=7 propagation steps
        g_Hc[((size_t)b * 8 + C) * NT + tau]  = h;
        g_PPc[((size_t)b * 8 + C) * NT + tau] = pp;
        h = fmaf(A32s[C], h, B32s[C] * pp);
        pp *= E32s[C];
    }
    g_mcoef[b * NT + tau] = -th * h * gq;
    g_A[b * NT + tid] = aRow[tid];
    g_B[b * NT + tid] = bRow[tid];
}

// =====================================================================
// Launch 4: invert 32x32 unit-lower diag blocks. D filled on the fly
// from G + local recurrence; Neumann product inverse (all GEMM).
// =====================================================================
__global__ __launch_bounds__(256, 1) void inv_kernel()
{
    __shared__ float Gd[32 * 33];
    __shared__ float evec[32], rvec[32], tvec[32];
    __shared__ __align__(16) float A0[32 * 36];
    __shared__ __align__(16) float A1[32 * 36];
    __shared__ __align__(16) float Xs[32 * 36];

    int tid = threadIdx.x;
    int b = blockIdx.x >> 3;
    int c = blockIdx.x & 7;
    const float* Gb = g_G + (size_t)b * NT * NT + (size_t)(32*c) * NT + 32*c;

#pragma unroll
    for (int rep = 0; rep < 4; ++rep) {
        int idx = rep * 256 + tid;
        int i2 = idx >> 5, j2 = idx & 31;
        Gd[i2 * 33 + j2] = Gb[(size_t)i2 * NT + j2];
        A0[i2 * 36 + j2] = 0.f;
        Xs[i2 * 36 + j2] = (i2 == j2) ? 1.f : 0.f;
    }
    if (tid < 32) {
        evec[tid] = g_eta[b * NT + 32*c + tid];
        rvec[tid] = 1.0f - g_alpha[b * NT + 32*c + tid];
        tvec[tid] = g_theta[b * NT + 32*c + tid];
    }
    __syncthreads();

    // fill strictly-lower D column per thread (local recurrence, no gmem)
    if (tid < 32) {
        int tau2 = tid;
        float th = tvec[tau2];
        float h = 1.f, pp = 1.f;
        for (int j2 = tau2 + 1; j2 < 32; ++j2) {
            float d = -th * Gd[j2 * 33 + tau2] * h;
            A0[j2 * 36 + tau2] = d;
            Xs[j2 * 36 + tau2] = d;
            pp *= evec[j2];
            h = fmaf(rvec[j2], h, pp);
        }
    }
    __syncthreads();

    int r = tid >> 3;
    int c0 = (tid & 7) * 4;
    float* Acur = A0;
    float* Anxt = A1;
#pragma unroll
    for (int it = 0; it < 4; ++it) {
        float4 acc = make_float4(0.f, 0.f, 0.f, 0.f);
#pragma unroll 8
        for (int kk = 0; kk < 32; ++kk) {
            float a = Acur[r * 36 + kk];
            float4 bv = *(const float4*)&Acur[kk * 36 + c0];
            acc.x = fmaf(a, bv.x, acc.x);
            acc.y = fmaf(a, bv.y, acc.y);
            acc.z = fmaf(a, bv.z, acc.z);
            acc.w = fmaf(a, bv.w, acc.w);
        }
        *(float4*)&Anxt[r * 36 + c0] = acc;
        __syncthreads();

        float4 xa = make_float4(0.f, 0.f, 0.f, 0.f);
#pragma unroll 8
        for (int kk = 0; kk < 32; ++kk) {
            float a = Xs[r * 36 + kk];
            float4 bv = *(const float4*)&Anxt[kk * 36 + c0];
            xa.x = fmaf(a, bv.x, xa.x);
            xa.y = fmaf(a, bv.y, xa.y);
            xa.z = fmaf(a, bv.z, xa.z);
            xa.w = fmaf(a, bv.w, xa.w);
        }
        __syncthreads();
        float4 xo = *(const float4*)&Xs[r * 36 + c0];
        xo.x += xa.x; xo.y += xa.y; xo.z += xa.z; xo.w += xa.w;
        *(float4*)&Xs[r * 36 + c0] = xo;
        __syncthreads();

        float* tmp = Acur; Acur = Anxt; Anxt = tmp;
    }

    float* Xo = g_X + (size_t)(b * 8 + c) * 1024;
#pragma unroll
    for (int rep = 0; rep < 4; ++rep) {
        int idx = rep * 256 + tid;
        Xo[idx] = Xs[(idx >> 5) * 36 + (idx & 31)];
    }
}

// =====================================================================
// Launch 5: z-solve (on-the-fly W from G) + head. One CTA per batch.
// =====================================================================
__global__ __launch_bounds__(256, 1) void zsolve_head_kernel(
    const float* __restrict__ W_f, const float* __restrict__ b_f,
    const float* __restrict__ W1,  const float* __restrict__ b1,
    const float* __restrict__ g1,  const float* __restrict__ be1,
    const float* __restrict__ W2,  const float* __restrict__ b2,
    float* __restrict__ out)
{
    __shared__ float sHc[8][NT];     // -theta-scaled boundary H
    __shared__ float sPPc[8][NT];    // -theta-scaled boundary PP
    __shared__ float sA[NT], sB[NT];
    __shared__ float Xc[32 * 33];
    __shared__ float zs[NT];
    __shared__ float mc[NT];
    __shared__ float rbuf[32];
    __shared__ float pbuf[8][33];
    __shared__ float zh[2 * ND];
    __shared__ float red[2 * ND];
    __shared__ float fusedv[ND];
    __shared__ float tbuf[ND];
    __shared__ float hh[ND];

    int tid = threadIdx.x;
    int b = blockIdx.x;
    const float* Gb = g_G + (size_t)b * NT * NT;

    // stage recurrence factors (-theta folded in)
    {
        float thv = g_theta[b * NT + tid];
        mc[tid] = g_mcoef[b * NT + tid];
        sA[tid] = g_A[b * NT + tid];
        sB[tid] = g_B[b * NT + tid];
#pragma unroll
        for (int C = 1; C < 8; ++C) {
            sHc[C][tid]  = -thv * g_Hc[((size_t)b * 8 + C) * NT + tid];
            sPPc[C][tid] = -thv * g_PPc[((size_t)b * 8 + C) * NT + tid];
        }
    }
    __syncthreads();

    int u = tid & 31, w = tid >> 5;

    // ---- back-substitution, chunk C = 7 .. 0 ----
    for (int C = 7; C >= 0; --C) {
        // stage X_C (used after the dot)
        {
            const float* Xo = g_X + ((size_t)b * 8 + C) * 1024;
#pragma unroll
            for (int rep = 0; rep < 4; ++rep) {
                int idx = rep * 256 + tid;
                Xc[(idx >> 5) * 33 + (idx & 31)] = Xo[idx];
            }
        }
        // rhs[u] += sum_{t >= 32(C+1)} W[t][32C+u]*z[t], W on the fly
        float acc = 0.f;
        int t0 = 32 * (C + 1);
        int nj = 4 * (7 - C);
        int tauc = 32 * C + u;
#pragma unroll 4
        for (int j = 0; j < nj; ++j) {
            int t = t0 + j * 8 + w;
            int Cr = t >> 5;
            float ht = fmaf(sA[t], sHc[Cr][tauc], sB[t] * sPPc[Cr][tauc]);
            float wv = Gb[(size_t)t * NT + tauc] * ht;
            acc = fmaf(wv, zs[t], acc);
        }
        pbuf[w][u] = acc;
        __syncthreads();
        if (tid < 32) {
            float s = mc[32*C + tid];
#pragma unroll
            for (int p = 0; p < 8; ++p) s += pbuf[p][tid];
            rbuf[tid] = s;
        }
        __syncthreads();
        // z_C = X_C^T rhs
        {
            float a = 0.f;
#pragma unroll
            for (int q = 0; q < 4; ++q) {
                int kk = w * 4 + q;
                a = fmaf(Xc[kk * 33 + u], rbuf[kk], a);
            }
            pbuf[w][u] = a;
        }
        __syncthreads();
        if (tid < 32) {
            float s = 0.f;
#pragma unroll
            for (int p = 0; p < 8; ++p) s += pbuf[p][tid];
            zs[32*C + tid] = s;
        }
        __syncthreads();
    }

    // ---- m_last = -V^T z (2-way K split) ----
    {
        int i = tid & 127, hf = tid >> 7;
        const float* vb = g_v + (size_t)b * NT * ND;
        float a = 0.f;
        int tb = hf * 128;
#pragma unroll 8
        for (int t = 0; t < 128; ++t)
            a = fmaf(vb[(size_t)(tb + t) * ND + i], zs[tb + t], a);
        red[hf * ND + i] = a;
    }
    __syncthreads();

    // ---- head ----
    if (tid < ND) {
        zh[ND + tid] = -(red[tid] + red[ND + tid]);
        zh[tid] = g_f[(size_t)(b * NT + NT - 1) * ND + tid];
    }
    __syncthreads();

    {
        int o = tid & 127, hf = tid >> 7;
        float acc = 0.f;
        int ib = hf * 128;
#pragma unroll 8
        for (int i = 0; i < 128; ++i)
            acc = fmaf(zh[ib + i], W_f[(size_t)(ib + i) * ND + o], acc);
        red[hf * ND + o] = acc;
    }
    __syncthreads();
    if (tid < ND) {
        float g = sigmoid_f(red[tid] + red[ND + tid] + b_f[tid]);
        fusedv[tid] = zh[tid] * g + zh[ND + tid] * (1.0f - g);
    }
    __syncthreads();

    {
        int o = tid & 127, hf = tid >> 7;
        float acc = 0.f;
        int ib = hf * 64;
#pragma unroll 8
        for (int i = 0; i < 64; ++i)
            acc = fmaf(fusedv[ib + i], W1[(size_t)(ib + i) * ND + o], acc);
        red[hf * ND + o] = acc;
    }
    __syncthreads();
    if (tid < ND) tbuf[tid] = red[tid] + red[ND + tid] + b1[tid];
    __syncthreads();

    float sum = 0.f, sq = 0.f;
#pragma unroll 8
    for (int i = 0; i < ND; ++i) { float t = tbuf[i]; sum += t; sq += t*t; }
    float mu = sum * (1.0f / ND);
    float var = sq * (1.0f / ND) - mu * mu;
    float rstd = rsqrtf(var + 1e-5f);
    if (tid < ND) {
        float ln = (tbuf[tid] - mu) * rstd * g1[tid] + be1[tid];
        hh[tid] = gelu_t(ln);
    }
    __syncthreads();

    for (int o = tid; o < NOUT; o += 256) {
        float acc = b2[o];
#pragma unroll 8
        for (int i = 0; i < ND; ++i)
            acc = fmaf(hh[i], W2[(size_t)i * NOUT + o], acc);
        out[b * NOUT + o] = acc;
    }
}

// ---------------- launch ----------------------------------------------------
extern "C" void kernel_launch(void* const* d_in, const int* in_sizes, int n_in,
                              void* d_out, int out_size)
{
    const float* x   = (const float*)d_in[0];
    const float* W_b = (const float*)d_in[1];
    const float* b_b = (const float*)d_in[2];
    const float* Wk  = (const float*)d_in[3];
    const float* Wv  = (const float*)d_in[4];
    const float* Wq  = (const float*)d_in[5];
    const float* W_m = (const float*)d_in[6];
    const float* b_m = (const float*)d_in[7];
    const float* W_f = (const float*)d_in[8];
    const float* b_f = (const float*)d_in[9];
    const float* W1  = (const float*)d_in[10];
    const float* b1  = (const float*)d_in[11];
    const float* g1  = (const float*)d_in[12];
    const float* be1 = (const float*)d_in[13];
    const float* W2  = (const float*)d_in[14];
    const float* b2  = (const float*)d_in[15];
    float* out = (float*)d_out;

    fgemm_kernel<<<dim3(32, 2), 256>>>(x, W_b, b_b);
    mega_kernel<<<392, 256>>>(Wk, Wv, Wq, W_m, b_m);
    gprep_kernel<<<NB * 17, 256>>>();
    inv_kernel<<<64, 256>>>();
    zsolve_head_kernel<<<NB, 256>>>(W_f, b_f, W1, b1, g1, be1, W2, b2, out);
}

// round 10
// speedup vs baseline: 1.7272x; 1.2003x over previous
#include <cuda_runtime.h>
#include <math.h>

#define NB 8
#define NT 256
#define NDI 64
#define ND 128
#define NROWS (NB*NT)
#define NOUT 672

__device__ float g_f[NROWS*ND];
__device__ float g_k[NROWS*ND];
__device__ float g_v[NROWS*ND];
__device__ float g_theta[NROWS];
__device__ float g_eta[NROWS];
__device__ float g_alpha[NROWS];
__device__ float g_qlast[NB*ND];
__device__ float g_G[NB*NT*NT];     // G[b][t][tau]
__device__ float g_X[NB*8*32*32];   // inverted diag blocks
__device__ float g_Gq[NB*NT];
__device__ int   g_ctr[16];

__device__ __forceinline__ float gelu_t(float x) {
    float x3 = x*x*x;
    return 0.5f*x*(1.0f + tanhf(0.79788456080286535588f*(x + 0.044715f*x3)));
}
__device__ __forceinline__ float sigmoid_f(float x) {
    return 1.0f/(1.0f + expf(-x));
}

// =====================================================================
// Launch 1: f = gelu(x @ W_b + b_b) + counter reset
// =====================================================================
__global__ __launch_bounds__(256) void fgemm_kernel(
    const float* __restrict__ A, const float* __restrict__ Bm,
    const float* __restrict__ bias)
{
    if (blockIdx.x == 0 && blockIdx.y == 0 && threadIdx.x < 16)
        g_ctr[threadIdx.x] = 0;

    __shared__ float As[16][64];
    __shared__ float Bs[16][64];
    int tid = threadIdx.x;
    int bm = blockIdx.x * 64, bn = blockIdx.y * 64;
    int ar = tid >> 2, ac = (tid & 3) * 4;
    int br = tid >> 4, bc = (tid & 15) * 4;
    int rm = (tid >> 4) * 4, rn = (tid & 15) * 4;

    float acc[4][4];
#pragma unroll
    for (int i = 0; i < 4; ++i)
#pragma unroll
        for (int j = 0; j < 4; ++j) acc[i][j] = 0.0f;

    for (int k0 = 0; k0 < NDI; k0 += 16) {
        float4 a = *(const float4*)(A + (size_t)(bm + ar) * NDI + k0 + ac);
        As[ac+0][ar]=a.x; As[ac+1][ar]=a.y; As[ac+2][ar]=a.z; As[ac+3][ar]=a.w;
        *(float4*)(&Bs[br][bc]) =
            *(const float4*)(Bm + (size_t)(k0 + br) * ND + bn + bc);
        __syncthreads();
#pragma unroll
        for (int kk = 0; kk < 16; ++kk) {
            float4 av = *(const float4*)(&As[kk][rm]);
            float4 bv = *(const float4*)(&Bs[kk][rn]);
            acc[0][0]=fmaf(av.x,bv.x,acc[0][0]); acc[0][1]=fmaf(av.x,bv.y,acc[0][1]);
            acc[0][2]=fmaf(av.x,bv.z,acc[0][2]); acc[0][3]=fmaf(av.x,bv.w,acc[0][3]);
            acc[1][0]=fmaf(av.y,bv.x,acc[1][0]); acc[1][1]=fmaf(av.y,bv.y,acc[1][1]);
            acc[1][2]=fmaf(av.y,bv.z,acc[1][2]); acc[1][3]=fmaf(av.y,bv.w,acc[1][3]);
            acc[2][0]=fmaf(av.z,bv.x,acc[2][0]); acc[2][1]=fmaf(av.z,bv.y,acc[2][1]);
            acc[2][2]=fmaf(av.z,bv.z,acc[2][2]); acc[2][3]=fmaf(av.z,bv.w,acc[2][3]);
            acc[3][0]=fmaf(av.w,bv.x,acc[3][0]); acc[3][1]=fmaf(av.w,bv.y,acc[3][1]);
            acc[3][2]=fmaf(av.w,bv.z,acc[3][2]); acc[3][3]=fmaf(av.w,bv.w,acc[3][3]);
        }
        __syncthreads();
    }
    float4 bb;
    bb.x=bias[bn+rn+0]; bb.y=bias[bn+rn+1]; bb.z=bias[bn+rn+2]; bb.w=bias[bn+rn+3];
#pragma unroll
    for (int i = 0; i < 4; ++i) {
        float4 o;
        o.x=gelu_t(acc[i][0]+bb.x); o.y=gelu_t(acc[i][1]+bb.y);
        o.z=gelu_t(acc[i][2]+bb.z); o.w=gelu_t(acc[i][3]+bb.w);
        *(float4*)(g_f + (size_t)(bm+rm+i) * ND + bn + rn) = o;
    }
}

// =====================================================================
// Launch 2: mega — k/v GEMM [0,128) + meta [128,384) + qlast [384,392)
// =====================================================================
__global__ __launch_bounds__(256) void mega_kernel(
    const float* __restrict__ Wk, const float* __restrict__ Wv,
    const float* __restrict__ Wq,
    const float* __restrict__ Wm, const float* __restrict__ bm_)
{
    __shared__ float smem_u[2 * 16 * 64];
    int idx = blockIdx.x, tid = threadIdx.x;

    if (idx < 128) {
        float (*As)[64] = (float(*)[64])smem_u;
        float (*Bs)[64] = (float(*)[64])(smem_u + 16 * 64);
        const float* Bm = (idx >> 6) ? Wv : Wk;
        float* C = (idx >> 6) ? g_v : g_k;
        int bm = (idx & 31) * 64, bn = ((idx >> 5) & 1) * 64;
        int ar = tid >> 2, ac = (tid & 3) * 4;
        int br = tid >> 4, bc = (tid & 15) * 4;
        int rm = (tid >> 4) * 4, rn = (tid & 15) * 4;

        float acc[4][4];
#pragma unroll
        for (int i = 0; i < 4; ++i)
#pragma unroll
            for (int j = 0; j < 4; ++j) acc[i][j] = 0.0f;

        for (int k0 = 0; k0 < ND; k0 += 16) {
            float4 a = *(const float4*)(g_f + (size_t)(bm + ar) * ND + k0 + ac);
            As[ac+0][ar]=a.x; As[ac+1][ar]=a.y; As[ac+2][ar]=a.z; As[ac+3][ar]=a.w;
            *(float4*)(&Bs[br][bc]) =
                *(const float4*)(Bm + (size_t)(k0 + br) * ND + bn + bc);
            __syncthreads();
#pragma unroll
            for (int kk = 0; kk < 16; ++kk) {
                float4 av = *(const float4*)(&As[kk][rm]);
                float4 bv = *(const float4*)(&Bs[kk][rn]);
                acc[0][0]=fmaf(av.x,bv.x,acc[0][0]); acc[0][1]=fmaf(av.x,bv.y,acc[0][1]);
                acc[0][2]=fmaf(av.x,bv.z,acc[0][2]); acc[0][3]=fmaf(av.x,bv.w,acc[0][3]);
                acc[1][0]=fmaf(av.y,bv.x,acc[1][0]); acc[1][1]=fmaf(av.y,bv.y,acc[1][1]);
                acc[1][2]=fmaf(av.y,bv.z,acc[1][2]); acc[1][3]=fmaf(av.y,bv.w,acc[1][3]);
                acc[2][0]=fmaf(av.z,bv.x,acc[2][0]); acc[2][1]=fmaf(av.z,bv.y,acc[2][1]);
                acc[2][2]=fmaf(av.z,bv.z,acc[2][2]); acc[2][3]=fmaf(av.z,bv.w,acc[2][3]);
                acc[3][0]=fmaf(av.w,bv.x,acc[3][0]); acc[3][1]=fmaf(av.w,bv.y,acc[3][1]);
                acc[3][2]=fmaf(av.w,bv.z,acc[3][2]); acc[3][3]=fmaf(av.w,bv.w,acc[3][3]);
            }
            __syncthreads();
        }
#pragma unroll
        for (int i = 0; i < 4; ++i) {
            float4 o; o.x=acc[i][0]; o.y=acc[i][1]; o.z=acc[i][2]; o.w=acc[i][3];
            *(float4*)(C + (size_t)(bm+rm+i) * ND + bn + rn) = o;
        }
    } else if (idx < 384) {
        int warp = tid >> 5, lane = tid & 31;
        int row = (idx - 128) * 8 + warp;
        const float4* f4 = (const float4*)g_f + (size_t)row * 32;
        float4 fv = f4[lane];
        const float* wp = Wm + lane * 12;
        float d0 = fv.x*wp[0] + fv.y*wp[3] + fv.z*wp[6] + fv.w*wp[9];
        float d1 = fv.x*wp[1] + fv.y*wp[4] + fv.z*wp[7] + fv.w*wp[10];
        float d2 = fv.x*wp[2] + fv.y*wp[5] + fv.z*wp[8] + fv.w*wp[11];
#pragma unroll
        for (int o = 16; o > 0; o >>= 1) {
            d0 += __shfl_xor_sync(0xffffffffu, d0, o);
            d1 += __shfl_xor_sync(0xffffffffu, d1, o);
            d2 += __shfl_xor_sync(0xffffffffu, d2, o);
        }
        if (lane == 0) {
            g_theta[row] = 0.01f * sigmoid_f(d0 + bm_[0]);
            g_eta[row]   =         sigmoid_f(d1 + bm_[1]);
            g_alpha[row] = 0.1f  * sigmoid_f(d2 + bm_[2]);
        }
    } else {
        int b = idx - 384;
        float* fl = smem_u;
        float* part = smem_u + 128;
        if (tid < ND) fl[tid] = g_f[(size_t)(b * NT + NT - 1) * ND + tid];
        __syncthreads();
        int j = tid & 127, h = tid >> 7;
        float acc = 0.f;
        int i0 = h * 64;
#pragma unroll 16
        for (int i = 0; i < 64; ++i)
            acc = fmaf(fl[i0 + i], Wq[(size_t)(i0 + i) * ND + j], acc);
        part[tid] = acc;
        __syncthreads();
        if (tid < ND) g_qlast[b * ND + j] = part[tid] + part[tid + 128];
    }
}

// =====================================================================
// Launch 3: EVERYTHING ELSE in one launch (136 CTAs, last-arriver).
//   r<16 : G tile (diag tiles also invert their two 32x32 blocks)
//   r=16 : Gq
//   last arriver per batch: coefs (smem) + z-solve + head.
// =====================================================================
__device__ void inv_block(int b, int c, float* pool, int tid)
{
    float* Gd = pool;            // 32*33
    float* A0 = pool + 1056;     // 32*36
    float* A1 = pool + 2208;
    float* Xs = pool + 3360;
    float* evec = pool + 4512;   // 32
    float* rvec = pool + 4544;
    float* tvec = pool + 4576;

    const float* Gb = g_G + (size_t)b * NT * NT + (size_t)(32*c) * NT + 32*c;

#pragma unroll
    for (int rep = 0; rep < 4; ++rep) {
        int idx = rep * 256 + tid;
        int i2 = idx >> 5, j2 = idx & 31;
        Gd[i2 * 33 + j2] = Gb[(size_t)i2 * NT + j2];
        A0[i2 * 36 + j2] = 0.f;
        Xs[i2 * 36 + j2] = (i2 == j2) ? 1.f : 0.f;
    }
    if (tid < 32) {
        evec[tid] = g_eta[b * NT + 32*c + tid];
        rvec[tid] = 1.0f - g_alpha[b * NT + 32*c + tid];
        tvec[tid] = g_theta[b * NT + 32*c + tid];
    }
    __syncthreads();

    if (tid < 32) {
        int tau2 = tid;
        float th = tvec[tau2];
        float h = 1.f, pp = 1.f;
        for (int j2 = tau2 + 1; j2 < 32; ++j2) {
            float d = -th * Gd[j2 * 33 + tau2] * h;
            A0[j2 * 36 + tau2] = d;
            Xs[j2 * 36 + tau2] = d;
            pp *= evec[j2];
            h = fmaf(rvec[j2], h, pp);
        }
    }
    __syncthreads();

    int r = tid >> 3;
    int c0 = (tid & 7) * 4;
    float* Acur = A0;
    float* Anxt = A1;
#pragma unroll
    for (int it = 0; it < 4; ++it) {
        float4 acc = make_float4(0.f, 0.f, 0.f, 0.f);
#pragma unroll 8
        for (int kk = 0; kk < 32; ++kk) {
            float a = Acur[r * 36 + kk];
            float4 bv = *(const float4*)&Acur[kk * 36 + c0];
            acc.x = fmaf(a, bv.x, acc.x);
            acc.y = fmaf(a, bv.y, acc.y);
            acc.z = fmaf(a, bv.z, acc.z);
            acc.w = fmaf(a, bv.w, acc.w);
        }
        *(float4*)&Anxt[r * 36 + c0] = acc;
        __syncthreads();

        float4 xa = make_float4(0.f, 0.f, 0.f, 0.f);
#pragma unroll 8
        for (int kk = 0; kk < 32; ++kk) {
            float a = Xs[r * 36 + kk];
            float4 bv = *(const float4*)&Anxt[kk * 36 + c0];
            xa.x = fmaf(a, bv.x, xa.x);
            xa.y = fmaf(a, bv.y, xa.y);
            xa.z = fmaf(a, bv.z, xa.z);
            xa.w = fmaf(a, bv.w, xa.w);
        }
        __syncthreads();
        float4 xo = *(const float4*)&Xs[r * 36 + c0];
        xo.x += xa.x; xo.y += xa.y; xo.z += xa.z; xo.w += xa.w;
        *(float4*)&Xs[r * 36 + c0] = xo;
        __syncthreads();

        float* tmp = Acur; Acur = Anxt; Anxt = tmp;
    }

    float* Xo = g_X + (size_t)(b * 8 + c) * 1024;
#pragma unroll
    for (int rep = 0; rep < 4; ++rep) {
        int idx = rep * 256 + tid;
        Xo[idx] = Xs[(idx >> 5) * 36 + (idx & 31)];
    }
    __syncthreads();
}

__global__ __launch_bounds__(256, 1) void gprep_all_kernel(
    const float* __restrict__ W_f, const float* __restrict__ b_f,
    const float* __restrict__ W1,  const float* __restrict__ b1,
    const float* __restrict__ g1,  const float* __restrict__ be1,
    const float* __restrict__ W2,  const float* __restrict__ b2,
    float* __restrict__ out)
{
    __shared__ __align__(16) float pool[7904];
    __shared__ int sflag;

    int b = blockIdx.x / 17;
    int r = blockIdx.x % 17;
    int tid = threadIdx.x;
    const float* Kb = g_k + (size_t)b * NT * ND;
    float* Gb = g_G + (size_t)b * NT * NT;

    if (r < 16) {
        // ---- G tile (I,J) ----
        float (*As)[64] = (float(*)[64])pool;
        float (*Bs)[64] = (float(*)[64])(pool + 16 * 64);
        int I = (r >> 2) * 64, J = (r & 3) * 64;
        int ar = tid >> 2, ac = (tid & 3) * 4;
        int rm = (tid >> 4) * 4, rn = (tid & 15) * 4;

        float acc[4][4];
#pragma unroll
        for (int i = 0; i < 4; ++i)
#pragma unroll
            for (int j = 0; j < 4; ++j) acc[i][j] = 0.0f;

        for (int k0 = 0; k0 < ND; k0 += 16) {
            float4 a = *(const float4*)(Kb + (size_t)(I + ar) * ND + k0 + ac);
            As[ac+0][ar]=a.x; As[ac+1][ar]=a.y; As[ac+2][ar]=a.z; As[ac+3][ar]=a.w;
            float4 bvec = *(const float4*)(Kb + (size_t)(J + ar) * ND + k0 + ac);
            Bs[ac+0][ar]=bvec.x; Bs[ac+1][ar]=bvec.y; Bs[ac+2][ar]=bvec.z; Bs[ac+3][ar]=bvec.w;
            __syncthreads();
#pragma unroll
            for (int kk = 0; kk < 16; ++kk) {
                float4 av = *(const float4*)(&As[kk][rm]);
                float4 bv = *(const float4*)(&Bs[kk][rn]);
                acc[0][0]=fmaf(av.x,bv.x,acc[0][0]); acc[0][1]=fmaf(av.x,bv.y,acc[0][1]);
                acc[0][2]=fmaf(av.x,bv.z,acc[0][2]); acc[0][3]=fmaf(av.x,bv.w,acc[0][3]);
                acc[1][0]=fmaf(av.y,bv.x,acc[1][0]); acc[1][1]=fmaf(av.y,bv.y,acc[1][1]);
                acc[1][2]=fmaf(av.y,bv.z,acc[1][2]); acc[1][3]=fmaf(av.y,bv.w,acc[1][3]);
                acc[2][0]=fmaf(av.z,bv.x,acc[2][0]); acc[2][1]=fmaf(av.z,bv.y,acc[2][1]);
                acc[2][2]=fmaf(av.z,bv.z,acc[2][2]); acc[2][3]=fmaf(av.z,bv.w,acc[2][3]);
                acc[3][0]=fmaf(av.w,bv.x,acc[3][0]); acc[3][1]=fmaf(av.w,bv.y,acc[3][1]);
                acc[3][2]=fmaf(av.w,bv.z,acc[3][2]); acc[3][3]=fmaf(av.w,bv.w,acc[3][3]);
            }
            __syncthreads();
        }
#pragma unroll
        for (int i = 0; i < 4; ++i) {
            float4 o; o.x=acc[i][0]; o.y=acc[i][1]; o.z=acc[i][2]; o.w=acc[i][3];
            *(float4*)(Gb + (size_t)(I+rm+i) * NT + J + rn) = o;
        }
        // diag tile: invert its two 32x32 blocks (G just written; syncthreads
        // orders the CTA's global writes for its own reads)
        if ((r >> 2) == (r & 3)) {
            __syncthreads();
            int q = r >> 2;
            inv_block(b, 2*q,     pool, tid);
            inv_block(b, 2*q + 1, pool, tid);
        }
    } else {
        // ---- Gq[t] = k_t . q ----
        float* qsm = pool;
        if (tid < ND) qsm[tid] = g_qlast[b * ND + tid];
        __syncthreads();
        const float* krow = Kb + (size_t)tid * ND;
        float acc = 0.f;
#pragma unroll 8
        for (int d = 0; d < ND; ++d) acc = fmaf(krow[d], qsm[d], acc);
        g_Gq[b * NT + tid] = acc;
    }

    // ---- last-arriver gate ----
    __threadfence();
    __syncthreads();
    if (tid == 0) sflag = atomicAdd(&g_ctr[8 + b], 1);
    __syncthreads();
    if (sflag != 16) return;
    __threadfence();

    // ================= tail: coefs + z-solve + head (one CTA/batch) =====
    float (*sHc)[NT]  = (float(*)[NT])(pool);          // [8][256]
    float (*sPPc)[NT] = (float(*)[NT])(pool + 2048);   // [8][256]
    float* sA    = pool + 4096;
    float* sB    = pool + 4352;
    float* mc    = pool + 4608;
    float* zvec  = pool + 4864;
    float* eta_s = pool + 5120;
    float* r_s   = pool + 5376;
    float* Xc    = pool + 5632;   // 32*33
    float* pbuff = pool + 6688;   // 8*33
    float* rbuf  = pool + 6952;   // 32
    float* zh    = pool + 6984;   // 256
    float* red   = pool + 7240;   // 256
    float* fusedv= pool + 7496;   // 128
    float* tbuf  = pool + 7624;   // 128
    float* hh    = pool + 7752;   // 128
    float* A32s  = pool + 7880;   // 8
    float* B32s  = pool + 7888;   // 8
    float* E32s  = pool + 7896;   // 8

    int tau = tid;
    __syncthreads();
    eta_s[tid] = g_eta[b * NT + tid];
    r_s[tid]   = 1.0f - g_alpha[b * NT + tid];
    float th   = g_theta[b * NT + tau];
    float gq   = g_Gq[b * NT + tau];
    __syncthreads();

    // per-chunk row constants
    if (tid < 8) {
        int c0 = tid * 32;
        float A = 1.f, Bv = 0.f, E = 1.f;
        for (int j = 0; j < 32; ++j) {
            sA[c0 + j] = A;
            sB[c0 + j] = Bv;
            E *= eta_s[c0 + j];
            Bv = fmaf(r_s[c0 + j], Bv, E);
            A *= r_s[c0 + j];
        }
        A32s[tid] = A; B32s[tid] = Bv; E32s[tid] = E;
    }
    __syncthreads();

    // per-tau boundary states (store -theta-scaled)
    {
        int Ct = tau >> 5;
        float h = 1.f, pp = 1.f;
        int c1 = 32 * (Ct + 1);
        for (int t = tau + 1; t < c1; ++t) {
            pp *= eta_s[t];
            h = fmaf(r_s[t], h, pp);
        }
        for (int C = Ct + 1; C < 8; ++C) {
            sHc[C][tau]  = -th * h;
            sPPc[C][tau] = -th * pp;
            h = fmaf(A32s[C], h, B32s[C] * pp);
            pp *= E32s[C];
        }
        mc[tau] = -th * h * gq;
    }
    __syncthreads();

    int u = tid & 31, w = tid >> 5;

    // ---- back-substitution, chunk C = 7 .. 0 ----
    for (int C = 7; C >= 0; --C) {
        {
            const float* Xo = g_X + ((size_t)b * 8 + C) * 1024;
#pragma unroll
            for (int rep = 0; rep < 4; ++rep) {
                int idx = rep * 256 + tid;
                Xc[(idx >> 5) * 33 + (idx & 31)] = Xo[idx];
            }
        }
        float acc = 0.f;
        int t0 = 32 * (C + 1);
        int nj = 4 * (7 - C);
        int tauc = 32 * C + u;
#pragma unroll 4
        for (int j = 0; j < nj; ++j) {
            int t = t0 + j * 8 + w;
            int Cr = t >> 5;
            float ht = fmaf(sA[t], sHc[Cr][tauc], sB[t] * sPPc[Cr][tauc]);
            float wv = Gb[(size_t)t * NT + tauc] * ht;
            acc = fmaf(wv, zvec[t], acc);
        }
        pbuff[w * 33 + u] = acc;
        __syncthreads();
        if (tid < 32) {
            float s = mc[32*C + tid];
#pragma unroll
            for (int p = 0; p < 8; ++p) s += pbuff[p * 33 + tid];
            rbuf[tid] = s;
        }
        __syncthreads();
        {
            float a = 0.f;
#pragma unroll
            for (int q2 = 0; q2 < 4; ++q2) {
                int kk = w * 4 + q2;
                a = fmaf(Xc[kk * 33 + u], rbuf[kk], a);
            }
            pbuff[w * 33 + u] = a;
        }
        __syncthreads();
        if (tid < 32) {
            float s = 0.f;
#pragma unroll
            for (int p = 0; p < 8; ++p) s += pbuff[p * 33 + tid];
            zvec[32*C + tid] = s;
        }
        __syncthreads();
    }

    // ---- m_last = -V^T z (2-way K split) ----
    {
        int i = tid & 127, hf = tid >> 7;
        const float* vb = g_v + (size_t)b * NT * ND;
        float a = 0.f;
        int tb = hf * 128;
#pragma unroll 8
        for (int t = 0; t < 128; ++t)
            a = fmaf(vb[(size_t)(tb + t) * ND + i], zvec[tb + t], a);
        red[hf * ND + i] = a;
    }
    __syncthreads();

    // ---- head ----
    if (tid < ND) {
        zh[ND + tid] = -(red[tid] + red[ND + tid]);
        zh[tid] = g_f[(size_t)(b * NT + NT - 1) * ND + tid];
    }
    __syncthreads();

    {
        int o = tid & 127, hf = tid >> 7;
        float acc = 0.f;
        int ib = hf * 128;
#pragma unroll 8
        for (int i = 0; i < 128; ++i)
            acc = fmaf(zh[ib + i], W_f[(size_t)(ib + i) * ND + o], acc);
        red[hf * ND + o] = acc;
    }
    __syncthreads();
    if (tid < ND) {
        float g = sigmoid_f(red[tid] + red[ND + tid] + b_f[tid]);
        fusedv[tid] = zh[tid] * g + zh[ND + tid] * (1.0f - g);
    }
    __syncthreads();

    {
        int o = tid & 127, hf = tid >> 7;
        float acc = 0.f;
        int ib = hf * 64;
#pragma unroll 8
        for (int i = 0; i < 64; ++i)
            acc = fmaf(fusedv[ib + i], W1[(size_t)(ib + i) * ND + o], acc);
        red[hf * ND + o] = acc;
    }
    __syncthreads();
    if (tid < ND) tbuf[tid] = red[tid] + red[ND + tid] + b1[tid];
    __syncthreads();

    float sum = 0.f, sq = 0.f;
#pragma unroll 8
    for (int i = 0; i < ND; ++i) { float t = tbuf[i]; sum += t; sq += t*t; }
    float mu = sum * (1.0f / ND);
    float var = sq * (1.0f / ND) - mu * mu;
    float rstd = rsqrtf(var + 1e-5f);
    if (tid < ND) {
        float ln = (tbuf[tid] - mu) * rstd * g1[tid] + be1[tid];
        hh[tid] = gelu_t(ln);
    }
    __syncthreads();

    for (int o = tid; o < NOUT; o += 256) {
        float acc = b2[o];
#pragma unroll 8
        for (int i = 0; i < ND; ++i)
            acc = fmaf(hh[i], W2[(size_t)i * NOUT + o], acc);
        out[b * NOUT + o] = acc;
    }
}

// ---------------- launch ----------------------------------------------------
extern "C" void kernel_launch(void* const* d_in, const int* in_sizes, int n_in,
                              void* d_out, int out_size)
{
    const float* x   = (const float*)d_in[0];
    const float* W_b = (const float*)d_in[1];
    const float* b_b = (const float*)d_in[2];
    const float* Wk  = (const float*)d_in[3];
    const float* Wv  = (const float*)d_in[4];
    const float* Wq  = (const float*)d_in[5];
    const float* W_m = (const float*)d_in[6];
    const float* b_m = (const float*)d_in[7];
    const float* W_f = (const float*)d_in[8];
    const float* b_f = (const float*)d_in[9];
    const float* W1  = (const float*)d_in[10];
    const float* b1  = (const float*)d_in[11];
    const float* g1  = (const float*)d_in[12];
    const float* be1 = (const float*)d_in[13];
    const float* W2  = (const float*)d_in[14];
    const float* b2  = (const float*)d_in[15];
    float* out = (float*)d_out;

    fgemm_kernel<<<dim3(32, 2), 256>>>(x, W_b, b_b);
    mega_kernel<<<392, 256>>>(Wk, Wv, Wq, W_m, b_m);
    gprep_all_kernel<<<NB * 17, 256>>>(W_f, b_f, W1, b1, g1, be1, W2, b2, out);
}